// round 8
// baseline (speedup 1.0000x reference)
#include <cuda_runtime.h>
#include <cuda_bf16.h>
#include <math.h>
#include <stdint.h>

#define D_MODEL   1024
#define NUM_HEADS 16
#define D_K       64
#define SEQ       2048
#define BATCH     2
#define M_TOK     (BATCH*SEQ)   // 4096

// ---------------- scratch (no allocation allowed) ----------------
__device__ float g_lin[3][(size_t)M_TOK * D_MODEL];                 // QKV linear outputs (fp32)

// bf16-split operands
__device__ __nv_bfloat16 g_xhi[(size_t)M_TOK * D_MODEL];
__device__ __nv_bfloat16 g_xlo[(size_t)M_TOK * D_MODEL];
__device__ __nv_bfloat16 g_whi[4][(size_t)D_MODEL * D_MODEL];
__device__ __nv_bfloat16 g_wlo[4][(size_t)D_MODEL * D_MODEL];
__device__ __nv_bfloat16 g_ahi[(size_t)M_TOK * D_MODEL];            // attn out hi
__device__ __nv_bfloat16 g_alo[(size_t)M_TOK * D_MODEL];            // attn out lo

// roped Q/K and V, bf16 hi/lo, [b,h,s,dk]
#define HSZ ((size_t)BATCH * NUM_HEADS * SEQ * D_K)
__device__ __nv_bfloat16 g_qhi[HSZ], g_qlo[HSZ];
__device__ __nv_bfloat16 g_khi[HSZ], g_klo[HSZ];
__device__ __nv_bfloat16 g_vhi[HSZ], g_vlo[HSZ];

// ---------------- helpers ----------------
__device__ __forceinline__ uint32_t smem_u32(const void* p) {
    uint32_t a;
    asm("{ .reg .u64 t; cvta.to.shared.u64 t, %1; cvt.u32.u64 %0, t; }" : "=r"(a) : "l"(p));
    return a;
}

__device__ __forceinline__ void cp_async16(uint32_t dst, const void* src) {
    asm volatile("cp.async.cg.shared.global [%0], [%1], 16;" :: "r"(dst), "l"(src));
}
#define CP_COMMIT() asm volatile("cp.async.commit_group;" ::: "memory")
#define CP_WAIT(n)  asm volatile("cp.async.wait_group %0;" :: "n"(n) : "memory")

__device__ __forceinline__ void ldmx4(uint32_t* r, uint32_t addr) {
    asm volatile("ldmatrix.sync.aligned.m8n8.x4.shared.b16 {%0,%1,%2,%3}, [%4];"
                 : "=r"(r[0]), "=r"(r[1]), "=r"(r[2]), "=r"(r[3]) : "r"(addr));
}

__device__ __forceinline__ void ldmx4t(uint32_t* r, uint32_t addr) {
    asm volatile("ldmatrix.sync.aligned.m8n8.x4.trans.shared.b16 {%0,%1,%2,%3}, [%4];"
                 : "=r"(r[0]), "=r"(r[1]), "=r"(r[2]), "=r"(r[3]) : "r"(addr));
}

__device__ __forceinline__ void mma_bf16(float* d, const uint32_t* a, const uint32_t* b) {
    asm volatile("mma.sync.aligned.m16n8k16.row.col.f32.bf16.bf16.f32 "
                 "{%0,%1,%2,%3}, {%4,%5,%6,%7}, {%8,%9}, {%0,%1,%2,%3};"
                 : "+f"(d[0]), "+f"(d[1]), "+f"(d[2]), "+f"(d[3])
                 : "r"(a[0]), "r"(a[1]), "r"(a[2]), "r"(a[3]), "r"(b[0]), "r"(b[1]));
}

__device__ __forceinline__ void split2(float a, float b, uint32_t& hi, uint32_t& lo) {
    __nv_bfloat162 h = __floats2bfloat162_rn(a, b);
    float ra = a - __bfloat162float(h.x);
    float rb = b - __bfloat162float(h.y);
    __nv_bfloat162 l = __floats2bfloat162_rn(ra, rb);
    hi = *(uint32_t*)&h;
    lo = *(uint32_t*)&l;
}

// BK=32 packed layout: logical row (64B) pairs share a 128B super-row.
// slot = 16B unit within row (0..3). Conflict-free for ldmatrix & cp.async.
__device__ __forceinline__ uint32_t sw32(uint32_t base, int row, int slot) {
    int sr = row >> 1;
    int c  = ((row & 1) << 2) + slot;
    return base + sr * 128 + ((c ^ (sr & 7)) << 4);
}

// ---------------- split conversion: fp32 -> (bf16 hi, bf16 lo) ----------------
__global__ void cvt_split_kernel(const float4* __restrict__ src,
                                 __nv_bfloat16* __restrict__ hi,
                                 __nv_bfloat16* __restrict__ lo, int n4)
{
    int i = blockIdx.x * blockDim.x + threadIdx.x;
    if (i >= n4) return;
    float4 v = src[i];
    __nv_bfloat16 h[4], l[4];
    float f[4] = {v.x, v.y, v.z, v.w};
#pragma unroll
    for (int j = 0; j < 4; j++) {
        h[j] = __float2bfloat16(f[j]);
        l[j] = __float2bfloat16(f[j] - __bfloat162float(h[j]));
    }
    *(uint2*)&hi[(size_t)i * 4] = *(uint2*)h;
    *(uint2*)&lo[(size_t)i * 4] = *(uint2*)l;
}

// ---------------- HMMA GEMM: C[M,N] = A[M,K] * W[N,K]^T (bf16 split, 3 MMAs) --------
// 128x128 tile, BK=32, 2-stage cp.async pipeline, 8 warps as 2(M)x4(N).
// Per stage: Ahi/Alo/Whi/Wlo 128x32 bf16 tiles (8KB each) = 32KB; 2 stages = 64KB.
#define GEMM_SMEM 65536
#define NCHUNK (D_MODEL / 32)   // 32

__device__ __forceinline__ void gemm_fill_stage(uint32_t stg,
                                                const __nv_bfloat16* const* srcs,
                                                int k0, int tid)
{
#pragma unroll
    for (int t = 0; t < 4; t++) {
        const __nv_bfloat16* S = srcs[t];
#pragma unroll
        for (int i = tid; i < 512; i += 256) {
            int r = i >> 2, sl = i & 3;
            cp_async16(sw32(stg + t * 8192, r, sl),
                       S + (size_t)r * D_MODEL + k0 + sl * 8);
        }
    }
}

__device__ __forceinline__ void mma_gemm_body(const __nv_bfloat16* __restrict__ Ahi,
                                              const __nv_bfloat16* __restrict__ Alo,
                                              const __nv_bfloat16* __restrict__ Whi,
                                              const __nv_bfloat16* __restrict__ Wlo,
                                              float* __restrict__ C)
{
    extern __shared__ char smem[];
    const uint32_t sb = smem_u32(smem);
    const int N = D_MODEL;
    const int bm = blockIdx.y * 128;
    const int bn = blockIdx.x * 128;
    const int tid  = threadIdx.x;
    const int wid  = tid >> 5;
    const int lane = tid & 31;
    const int wm = (wid >> 2) * 64;
    const int wn = (wid & 3) * 32;

    const __nv_bfloat16* srcs[4] = {
        Ahi + (size_t)bm * D_MODEL, Alo + (size_t)bm * D_MODEL,
        Whi + (size_t)bn * D_MODEL, Wlo + (size_t)bn * D_MODEL };

    float acc[4][4][4];
#pragma unroll
    for (int i = 0; i < 4; i++)
#pragma unroll
        for (int j = 0; j < 4; j++)
#pragma unroll
            for (int e = 0; e < 4; e++) acc[i][j][e] = 0.f;

    const int rA = (lane & 7) + ((lane >> 3) & 1) * 8;
    const int pA = (lane >> 4) & 1;

    // prime stage 0 with chunk 0
    gemm_fill_stage(sb, srcs, 0, tid);
    CP_COMMIT();

    for (int c = 0; c < NCHUNK; ++c) {
        const uint32_t stg = sb + (uint32_t)(c & 1) * 32768;
        const bool pf = (c + 1 < NCHUNK);
        if (pf) {
            // stage (c+1)&1 was released by the trailing sync of iteration c-1
            gemm_fill_stage(sb + (uint32_t)((c + 1) & 1) * 32768, srcs, (c + 1) * 32, tid);
            CP_COMMIT();
        }
        if (pf) { CP_WAIT(1); } else { CP_WAIT(0); }   // chunk c resident
        __syncthreads();

#pragma unroll
        for (int ks = 0; ks < 2; ks++) {
            const int slot = ks * 2 + pA;
            uint32_t ah[4][4], al[4][4], bh[4][2], bl[4][2];
#pragma unroll
            for (int im = 0; im < 4; im++) {
                int row = wm + im * 16 + rA;
                ldmx4(ah[im], sw32(stg,        row, slot));
                ldmx4(al[im], sw32(stg + 8192, row, slot));
            }
#pragma unroll
            for (int g = 0; g < 2; g++) {
                int row = wn + g * 16 + rA;
                uint32_t t0[4], t1[4];
                ldmx4(t0, sw32(stg + 16384, row, slot));
                ldmx4(t1, sw32(stg + 24576, row, slot));
                bh[g * 2 + 0][0] = t0[0]; bh[g * 2 + 0][1] = t0[2];
                bh[g * 2 + 1][0] = t0[1]; bh[g * 2 + 1][1] = t0[3];
                bl[g * 2 + 0][0] = t1[0]; bl[g * 2 + 0][1] = t1[2];
                bl[g * 2 + 1][0] = t1[1]; bl[g * 2 + 1][1] = t1[3];
            }
#pragma unroll
            for (int im = 0; im < 4; im++)
#pragma unroll
                for (int jn = 0; jn < 4; jn++) {
                    mma_bf16(acc[im][jn], ah[im], bh[jn]);
                    mma_bf16(acc[im][jn], ah[im], bl[jn]);
                    mma_bf16(acc[im][jn], al[im], bh[jn]);
                }
        }
        __syncthreads();   // all warps done reading stage c&1 before it is refilled
    }

    const int r0 = bm + wm + (lane >> 2);
    const int c0 = bn + wn + (lane & 3) * 2;
#pragma unroll
    for (int im = 0; im < 4; im++)
#pragma unroll
        for (int jn = 0; jn < 4; jn++) {
            float* p0 = C + (size_t)(r0 + im * 16) * N + c0 + jn * 8;
            float* p1 = C + (size_t)(r0 + im * 16 + 8) * N + c0 + jn * 8;
            *(float2*)p0 = make_float2(acc[im][jn][0], acc[im][jn][1]);
            *(float2*)p1 = make_float2(acc[im][jn][2], acc[im][jn][3]);
        }
}

__global__ void __launch_bounds__(256) qkv_mma_kernel()
{
    const int z = blockIdx.z;
    mma_gemm_body(g_xhi, g_xlo, &g_whi[z][0], &g_wlo[z][0], &g_lin[z][0]);
}

__global__ void __launch_bounds__(256) out_mma_kernel(float* __restrict__ out)
{
    mma_gemm_body(g_ahi, g_alo, &g_whi[3][0], &g_wlo[3][0], out);
}

// ---------------- RoPE + reshape to [b,h,s,dk], bf16 hi/lo output ----------------
__global__ void rope_kernel(const int* __restrict__ pos)
{
    const int z   = blockIdx.z;                         // 0=Q (rope+scale), 1=K (rope), 2=V (copy)
    const int idx = blockIdx.x * blockDim.x + threadIdx.x;
    const int j     = idx & 31;
    const int h     = (idx >> 5) & 15;
    const int chunk = (idx >> 9) & 63;
    const int b     = (idx >> 15) & 1;

    const float* src_base = &g_lin[z][0] + ((size_t)b * SEQ) * D_MODEL + h * 64 + 2 * j;
    __nv_bfloat16* dhi = (z == 0) ? g_qhi : (z == 1) ? g_khi : g_vhi;
    __nv_bfloat16* dlo = (z == 0) ? g_qlo : (z == 1) ? g_klo : g_vlo;
    const size_t dst_off = ((size_t)(b * NUM_HEADS + h) * SEQ) * D_K + 2 * j;
    const int s0 = chunk * 32;

    if (z == 2) {
        for (int ss = 0; ss < 32; ss++) {
            int s = s0 + ss;
            const float* sp = src_base + (size_t)s * D_MODEL;
            uint32_t hi, lo;
            split2(sp[0], sp[1], hi, lo);
            size_t o = dst_off + (size_t)s * D_K;
            *(uint32_t*)(dhi + o) = hi;
            *(uint32_t*)(dlo + o) = lo;
        }
    } else {
        const double freq   = exp((double)j * -0.28782313662425575);
        const double inv2pi = 0.15915494309189535;
        const double twopi  = 6.283185307179586;
        const float qscale = (z == 0) ? 0.125f : 1.0f;
        for (int ss = 0; ss < 32; ss++) {
            int s = s0 + ss;
            double ang = (double)pos[s] * freq;
            ang -= trunc(ang * inv2pi) * twopi;
            float c, sn;
            sincosf((float)ang, &sn, &c);
            const float* sp = src_base + (size_t)s * D_MODEL;
            float x1 = sp[0], x2 = sp[1];
            float r1 = (x1 * c - x2 * sn) * qscale;
            float r2 = (x1 * sn + x2 * c) * qscale;
            uint32_t hi, lo;
            split2(r1, r2, hi, lo);
            size_t o = dst_off + (size_t)s * D_K;
            *(uint32_t*)(dhi + o) = hi;
            *(uint32_t*)(dlo + o) = lo;
        }
    }
}

// ---------------- Flash attention (causal, HMMA bf16-split, 2-stage cp.async) --------
#define KH 0
#define KL 8192
#define VH 16384
#define VL 24576
#define FLASH_SMEM 65536

__global__ void __launch_bounds__(128) flash_kernel()
{
    extern __shared__ __align__(16) char fsm[];
    const uint32_t sb = smem_u32(fsm);

    const int qt = blockIdx.x;
    const int h  = blockIdx.y;
    const int bb = blockIdx.z;
    const int tid  = threadIdx.x;
    const int wid  = tid >> 5;
    const int lane = tid & 31;

    const size_t hoff = (size_t)(bb * NUM_HEADS + h) * SEQ * D_K;
    const __nv_bfloat16* Qh = g_qhi + hoff;
    const __nv_bfloat16* Ql = g_qlo + hoff;
    const __nv_bfloat16* Kh = g_khi + hoff;
    const __nv_bfloat16* Kl = g_klo + hoff;
    const __nv_bfloat16* Vh = g_vhi + hoff;
    const __nv_bfloat16* Vl = g_vlo + hoff;
    const int q0 = qt * 64;

    const int rA = (lane & 7) + 8 * ((lane >> 3) & 1);
    const int pA = (lane >> 4) & 1;

    for (int i = tid; i < 512; i += 128) {
        int r = i >> 3, ch = i & 7;
        int sw = r * 128 + ((ch ^ (r & 7)) << 4);
        size_t gix = (size_t)(q0 + r) * D_K + ch * 8;
        cp_async16(sb + 32768 + KH + sw, Qh + gix);
        cp_async16(sb + 32768 + KL + sw, Ql + gix);
    }
    CP_COMMIT();
    for (int i = tid; i < 512; i += 128) {
        int r = i >> 3, ch = i & 7;
        int sw = r * 128 + ((ch ^ (r & 7)) << 4);
        size_t gix = (size_t)r * D_K + ch * 8;
        cp_async16(sb + KH + sw, Kh + gix);
        cp_async16(sb + KL + sw, Kl + gix);
        cp_async16(sb + VH + sw, Vh + gix);
        cp_async16(sb + VL + sw, Vl + gix);
    }
    CP_COMMIT();

    CP_WAIT(1);
    __syncthreads();

    uint32_t aq[4][4], aql[4][4];
#pragma unroll
    for (int ks = 0; ks < 4; ks++) {
        int slot = ks * 2 + pA;
        int row  = wid * 16 + rA;
        uint32_t ad = sb + 32768 + KH + row * 128 + ((slot ^ (row & 7)) << 4);
        ldmx4(aq[ks], ad);
        ldmx4(aql[ks], ad + (KL - KH));
    }

    float out[8][4];
#pragma unroll
    for (int g = 0; g < 8; g++)
#pragma unroll
        for (int e = 0; e < 4; e++) out[g][e] = 0.f;
    float m0 = -1e30f, m1 = -1e30f, l0 = 0.f, l1 = 0.f;

    for (int kt = 0; kt <= qt; kt++) {
        const uint32_t sbs = sb + (uint32_t)(kt & 1) * 32768;
        CP_WAIT(0);
        __syncthreads();

        if (kt < qt) {
            const uint32_t sbn = sb + (uint32_t)((kt + 1) & 1) * 32768;
            for (int i = tid; i < 512; i += 128) {
                int r = i >> 3, ch = i & 7;
                int sw = r * 128 + ((ch ^ (r & 7)) << 4);
                size_t gix = (size_t)((kt + 1) * 64 + r) * D_K + ch * 8;
                cp_async16(sbn + KH + sw, Kh + gix);
                cp_async16(sbn + KL + sw, Kl + gix);
                cp_async16(sbn + VH + sw, Vh + gix);
                cp_async16(sbn + VL + sw, Vl + gix);
            }
            CP_COMMIT();
        }

        float s[8][4];
#pragma unroll
        for (int g = 0; g < 8; g++)
#pragma unroll
            for (int e = 0; e < 4; e++) s[g][e] = 0.f;

#pragma unroll
        for (int ks = 0; ks < 4; ks++) {
            const int slot = ks * 2 + pA;
            uint32_t bh[8][2], bl[8][2];
#pragma unroll
            for (int g2 = 0; g2 < 4; g2++) {
                int row = g2 * 16 + rA;
                uint32_t bd = sbs + KH + row * 128 + ((slot ^ (row & 7)) << 4);
                uint32_t t0[4], t1[4];
                ldmx4(t0, bd);
                ldmx4(t1, bd + (KL - KH));
                bh[g2 * 2 + 0][0] = t0[0]; bh[g2 * 2 + 0][1] = t0[2];
                bh[g2 * 2 + 1][0] = t0[1]; bh[g2 * 2 + 1][1] = t0[3];
                bl[g2 * 2 + 0][0] = t1[0]; bl[g2 * 2 + 0][1] = t1[2];
                bl[g2 * 2 + 1][0] = t1[1]; bl[g2 * 2 + 1][1] = t1[3];
            }
#pragma unroll
            for (int g = 0; g < 8; g++) {
                mma_bf16(s[g], aq[ks], bh[g]);
                mma_bf16(s[g], aq[ks], bl[g]);
                mma_bf16(s[g], aql[ks], bh[g]);
            }
        }

        if (kt == qt) {
            int r0 = wid * 16 + (lane >> 2);
#pragma unroll
            for (int g = 0; g < 8; g++) {
                int cb = 8 * g + 2 * (lane & 3);
                if (cb     > r0)     s[g][0] = -1e30f;
                if (cb + 1 > r0)     s[g][1] = -1e30f;
                if (cb     > r0 + 8) s[g][2] = -1e30f;
                if (cb + 1 > r0 + 8) s[g][3] = -1e30f;
            }
        }

        float mx0 = -1e30f, mx1 = -1e30f;
#pragma unroll
        for (int g = 0; g < 8; g++) {
            mx0 = fmaxf(mx0, fmaxf(s[g][0], s[g][1]));
            mx1 = fmaxf(mx1, fmaxf(s[g][2], s[g][3]));
        }
        mx0 = fmaxf(mx0, __shfl_xor_sync(0xffffffffu, mx0, 1));
        mx0 = fmaxf(mx0, __shfl_xor_sync(0xffffffffu, mx0, 2));
        mx1 = fmaxf(mx1, __shfl_xor_sync(0xffffffffu, mx1, 1));
        mx1 = fmaxf(mx1, __shfl_xor_sync(0xffffffffu, mx1, 2));

        float mn0 = fmaxf(m0, mx0), mn1 = fmaxf(m1, mx1);
        float sf0 = __expf(m0 - mn0), sf1 = __expf(m1 - mn1);
        m0 = mn0; m1 = mn1;

        float rs0 = 0.f, rs1 = 0.f;
#pragma unroll
        for (int g = 0; g < 8; g++) {
            s[g][0] = __expf(s[g][0] - mn0);
            s[g][1] = __expf(s[g][1] - mn0);
            s[g][2] = __expf(s[g][2] - mn1);
            s[g][3] = __expf(s[g][3] - mn1);
            rs0 += s[g][0] + s[g][1];
            rs1 += s[g][2] + s[g][3];
        }
        rs0 += __shfl_xor_sync(0xffffffffu, rs0, 1);
        rs0 += __shfl_xor_sync(0xffffffffu, rs0, 2);
        rs1 += __shfl_xor_sync(0xffffffffu, rs1, 1);
        rs1 += __shfl_xor_sync(0xffffffffu, rs1, 2);
        l0 = l0 * sf0 + rs0;
        l1 = l1 * sf1 + rs1;
#pragma unroll
        for (int g = 0; g < 8; g++) {
            out[g][0] *= sf0; out[g][1] *= sf0;
            out[g][2] *= sf1; out[g][3] *= sf1;
        }

        uint32_t ap[4][4], apl[4][4];
#pragma unroll
        for (int j = 0; j < 4; j++) {
            split2(s[2*j][0],   s[2*j][1],   ap[j][0], apl[j][0]);
            split2(s[2*j][2],   s[2*j][3],   ap[j][1], apl[j][1]);
            split2(s[2*j+1][0], s[2*j+1][1], ap[j][2], apl[j][2]);
            split2(s[2*j+1][2], s[2*j+1][3], ap[j][3], apl[j][3]);
        }

#pragma unroll
        for (int j = 0; j < 4; j++) {
            uint32_t bv[8][2], bvl[8][2];
            int krow = j * 16 + (lane & 7) + 8 * ((lane >> 3) & 1);
            int colh = (lane >> 4) & 1;
#pragma unroll
            for (int dp = 0; dp < 4; dp++) {
                int slot = dp * 2 + colh;
                uint32_t ad = sbs + VH + krow * 128 + ((slot ^ (krow & 7)) << 4);
                uint32_t t0[4], t1[4];
                ldmx4t(t0, ad);
                ldmx4t(t1, ad + (VL - VH));
                bv[dp * 2 + 0][0] = t0[0]; bv[dp * 2 + 0][1] = t0[1];
                bv[dp * 2 + 1][0] = t0[2]; bv[dp * 2 + 1][1] = t0[3];
                bvl[dp * 2 + 0][0] = t1[0]; bvl[dp * 2 + 0][1] = t1[1];
                bvl[dp * 2 + 1][0] = t1[2]; bvl[dp * 2 + 1][1] = t1[3];
            }
#pragma unroll
            for (int g = 0; g < 8; g++) {
                mma_bf16(out[g], ap[j], bv[g]);
                mma_bf16(out[g], ap[j], bvl[g]);
                mma_bf16(out[g], apl[j], bv[g]);
            }
        }
    }

    float inv0 = 1.f / l0, inv1 = 1.f / l1;
    int srow = q0 + wid * 16 + (lane >> 2);
    size_t base0 = ((size_t)(bb * SEQ) + srow) * D_MODEL + h * 64;
    size_t base1 = base0 + (size_t)8 * D_MODEL;
#pragma unroll
    for (int g = 0; g < 8; g++) {
        int d = 8 * g + 2 * (lane & 3);
        uint32_t hi, lo;
        split2(out[g][0] * inv0, out[g][1] * inv0, hi, lo);
        *(uint32_t*)(g_ahi + base0 + d) = hi;
        *(uint32_t*)(g_alo + base0 + d) = lo;
        split2(out[g][2] * inv1, out[g][3] * inv1, hi, lo);
        *(uint32_t*)(g_ahi + base1 + d) = hi;
        *(uint32_t*)(g_alo + base1 + d) = lo;
    }
}

// ---------------- launch ----------------
extern "C" void kernel_launch(void* const* d_in, const int* in_sizes, int n_in,
                              void* d_out, int out_size)
{
    const float* x   = (const float*)d_in[0];
    const int*   pos = (const int*)  d_in[1];
    const float* wq  = (const float*)d_in[2];
    const float* wk  = (const float*)d_in[3];
    const float* wv  = (const float*)d_in[4];
    const float* wo  = (const float*)d_in[5];
    float* out = (float*)d_out;

    (void)in_sizes; (void)n_in; (void)out_size;

    static bool attr_done = false;
    if (!attr_done) {
        cudaFuncSetAttribute(qkv_mma_kernel, cudaFuncAttributeMaxDynamicSharedMemorySize,
                             GEMM_SMEM);
        cudaFuncSetAttribute(out_mma_kernel, cudaFuncAttributeMaxDynamicSharedMemorySize,
                             GEMM_SMEM);
        cudaFuncSetAttribute(flash_kernel, cudaFuncAttributeMaxDynamicSharedMemorySize,
                             FLASH_SMEM);
        attr_done = true;
    }

    __nv_bfloat16 *xhi, *xlo, *whi0, *wlo0;
    cudaGetSymbolAddress((void**)&xhi,  g_xhi);
    cudaGetSymbolAddress((void**)&xlo,  g_xlo);
    cudaGetSymbolAddress((void**)&whi0, g_whi);
    cudaGetSymbolAddress((void**)&wlo0, g_wlo);

    const int n4x = M_TOK * D_MODEL / 4;
    const int n4w = D_MODEL * D_MODEL / 4;
    const size_t wsz = (size_t)D_MODEL * D_MODEL;

    cvt_split_kernel<<<(n4x + 255) / 256, 256>>>((const float4*)x, xhi, xlo, n4x);
    cvt_split_kernel<<<(n4w + 255) / 256, 256>>>((const float4*)wq, whi0, wlo0, n4w);
    cvt_split_kernel<<<(n4w + 255) / 256, 256>>>((const float4*)wk, whi0 + wsz, wlo0 + wsz, n4w);
    cvt_split_kernel<<<(n4w + 255) / 256, 256>>>((const float4*)wv, whi0 + 2 * wsz, wlo0 + 2 * wsz, n4w);
    cvt_split_kernel<<<(n4w + 255) / 256, 256>>>((const float4*)wo, whi0 + 3 * wsz, wlo0 + 3 * wsz, n4w);

    qkv_mma_kernel<<<dim3(D_MODEL / 128, M_TOK / 128, 3), 256, GEMM_SMEM>>>();
    rope_kernel<<<dim3(256, 1, 3), 256>>>(pos);
    flash_kernel<<<dim3(SEQ / 64, NUM_HEADS, BATCH), 128, FLASH_SMEM>>>();
    out_mma_kernel<<<dim3(D_MODEL / 128, M_TOK / 128, 1), 256, GEMM_SMEM>>>(out);
}

// round 9
// speedup vs baseline: 1.0380x; 1.0380x over previous
#include <cuda_runtime.h>
#include <cuda_bf16.h>
#include <math.h>
#include <stdint.h>

#define D_MODEL   1024
#define NUM_HEADS 16
#define D_K       64
#define SEQ       2048
#define BATCH     2
#define M_TOK     (BATCH*SEQ)   // 4096

// ---------------- scratch (no allocation allowed) ----------------
__device__ float g_lin[3][(size_t)M_TOK * D_MODEL];                 // QKV linear outputs (fp32)

// bf16-split operands
__device__ __nv_bfloat16 g_xhi[(size_t)M_TOK * D_MODEL];
__device__ __nv_bfloat16 g_xlo[(size_t)M_TOK * D_MODEL];
__device__ __nv_bfloat16 g_whi[4][(size_t)D_MODEL * D_MODEL];
__device__ __nv_bfloat16 g_wlo[4][(size_t)D_MODEL * D_MODEL];
__device__ __nv_bfloat16 g_ahi[(size_t)M_TOK * D_MODEL];            // attn out hi
__device__ __nv_bfloat16 g_alo[(size_t)M_TOK * D_MODEL];            // attn out lo

// roped Q/K and V, bf16 hi/lo, [b,h,s,dk]
#define HSZ ((size_t)BATCH * NUM_HEADS * SEQ * D_K)
__device__ __nv_bfloat16 g_qhi[HSZ], g_qlo[HSZ];
__device__ __nv_bfloat16 g_khi[HSZ], g_klo[HSZ];
__device__ __nv_bfloat16 g_vhi[HSZ], g_vlo[HSZ];

// ---------------- helpers ----------------
__device__ __forceinline__ uint32_t smem_u32(const void* p) {
    uint32_t a;
    asm("{ .reg .u64 t; cvta.to.shared.u64 t, %1; cvt.u32.u64 %0, t; }" : "=r"(a) : "l"(p));
    return a;
}

__device__ __forceinline__ void cp_async16(uint32_t dst, const void* src) {
    asm volatile("cp.async.cg.shared.global [%0], [%1], 16;" :: "r"(dst), "l"(src));
}
#define CP_COMMIT() asm volatile("cp.async.commit_group;" ::: "memory")
#define CP_WAIT(n)  asm volatile("cp.async.wait_group %0;" :: "n"(n) : "memory")

__device__ __forceinline__ void ldmx4(uint32_t* r, uint32_t addr) {
    asm volatile("ldmatrix.sync.aligned.m8n8.x4.shared.b16 {%0,%1,%2,%3}, [%4];"
                 : "=r"(r[0]), "=r"(r[1]), "=r"(r[2]), "=r"(r[3]) : "r"(addr));
}

__device__ __forceinline__ void ldmx4t(uint32_t* r, uint32_t addr) {
    asm volatile("ldmatrix.sync.aligned.m8n8.x4.trans.shared.b16 {%0,%1,%2,%3}, [%4];"
                 : "=r"(r[0]), "=r"(r[1]), "=r"(r[2]), "=r"(r[3]) : "r"(addr));
}

__device__ __forceinline__ void mma_bf16(float* d, const uint32_t* a, const uint32_t* b) {
    asm volatile("mma.sync.aligned.m16n8k16.row.col.f32.bf16.bf16.f32 "
                 "{%0,%1,%2,%3}, {%4,%5,%6,%7}, {%8,%9}, {%0,%1,%2,%3};"
                 : "+f"(d[0]), "+f"(d[1]), "+f"(d[2]), "+f"(d[3])
                 : "r"(a[0]), "r"(a[1]), "r"(a[2]), "r"(a[3]), "r"(b[0]), "r"(b[1]));
}

__device__ __forceinline__ void split2(float a, float b, uint32_t& hi, uint32_t& lo) {
    __nv_bfloat162 h = __floats2bfloat162_rn(a, b);
    float ra = a - __bfloat162float(h.x);
    float rb = b - __bfloat162float(h.y);
    __nv_bfloat162 l = __floats2bfloat162_rn(ra, rb);
    hi = *(uint32_t*)&h;
    lo = *(uint32_t*)&l;
}

// ---------------- split conversion: fp32 -> (bf16 hi, bf16 lo) ----------------
__global__ void cvt_split_kernel(const float4* __restrict__ src,
                                 __nv_bfloat16* __restrict__ hi,
                                 __nv_bfloat16* __restrict__ lo, int n4)
{
    int i = blockIdx.x * blockDim.x + threadIdx.x;
    if (i >= n4) return;
    float4 v = src[i];
    __nv_bfloat16 h[4], l[4];
    float f[4] = {v.x, v.y, v.z, v.w};
#pragma unroll
    for (int j = 0; j < 4; j++) {
        h[j] = __float2bfloat16(f[j]);
        l[j] = __float2bfloat16(f[j] - __bfloat162float(h[j]));
    }
    *(uint2*)&hi[(size_t)i * 4] = *(uint2*)h;
    *(uint2*)&lo[(size_t)i * 4] = *(uint2*)l;
}

// ---------------- HMMA GEMM: C[M,N] = A[M,K] * W[N,K]^T (bf16 split, 3 MMAs) --------
// 128x128 tile, BK=64 (R7-proven layout), 2-stage cp.async pipeline (64KB stages).
// Per stage: Ahi/Alo/Whi/Wlo 128x64 bf16 tiles (16KB each) = 64KB; 2 stages = 128KB.
#define GEMM_SMEM 131072
#define STAGE_SZ  65536

__device__ __forceinline__ void gemm_fill_stage(uint32_t stg,
                                                const __nv_bfloat16* const* srcs,
                                                int k0, int tid)
{
#pragma unroll
    for (int t = 0; t < 4; t++) {
        const __nv_bfloat16* S = srcs[t];
#pragma unroll
        for (int i = tid; i < 1024; i += 256) {
            int row = i >> 3, slot = i & 7;
            cp_async16(stg + t * 16384 + row * 128 + ((slot ^ (row & 7)) << 4),
                       S + (size_t)row * D_MODEL + k0 + slot * 8);
        }
    }
}

__device__ __forceinline__ void mma_gemm_body(const __nv_bfloat16* __restrict__ Ahi,
                                              const __nv_bfloat16* __restrict__ Alo,
                                              const __nv_bfloat16* __restrict__ Whi,
                                              const __nv_bfloat16* __restrict__ Wlo,
                                              float* __restrict__ C)
{
    extern __shared__ char smem[];
    const uint32_t sb = smem_u32(smem);
    const int N = D_MODEL;
    const int bm = blockIdx.y * 128;
    const int bn = blockIdx.x * 128;
    const int tid  = threadIdx.x;
    const int wid  = tid >> 5;
    const int lane = tid & 31;
    const int wm = (wid >> 2) * 64;
    const int wn = (wid & 3) * 32;

    const __nv_bfloat16* srcs[4] = {
        Ahi + (size_t)bm * D_MODEL, Alo + (size_t)bm * D_MODEL,
        Whi + (size_t)bn * D_MODEL, Wlo + (size_t)bn * D_MODEL };

    float acc[4][4][4];
#pragma unroll
    for (int i = 0; i < 4; i++)
#pragma unroll
        for (int j = 0; j < 4; j++)
#pragma unroll
            for (int e = 0; e < 4; e++) acc[i][j][e] = 0.f;

    const int rA = (lane & 7) + ((lane >> 3) & 1) * 8;
    const int pA = (lane >> 4) & 1;

    // prime stage 0 with chunk 0
    gemm_fill_stage(sb, srcs, 0, tid);
    CP_COMMIT();

    for (int c = 0; c < 16; ++c) {
        const uint32_t stg = sb + (uint32_t)(c & 1) * STAGE_SZ;
        const bool pf = (c + 1 < 16);
        if (pf) {
            // stage (c+1)&1 was released by the trailing sync of iteration c-1
            gemm_fill_stage(sb + (uint32_t)((c + 1) & 1) * STAGE_SZ, srcs,
                            (c + 1) * 64, tid);
            CP_COMMIT();
        }
        if (pf) { CP_WAIT(1); } else { CP_WAIT(0); }   // chunk c resident
        __syncthreads();

#pragma unroll
        for (int kk = 0; kk < 4; kk++) {
            const int slot = kk * 2 + pA;
            uint32_t ah[4][4], al[4][4], bh[4][2], bl[4][2];
#pragma unroll
            for (int im = 0; im < 4; im++) {
                int row = wm + im * 16 + rA;
                uint32_t ad = stg + row * 128 + ((slot ^ (row & 7)) << 4);
                ldmx4(ah[im], ad);
                ldmx4(al[im], ad + 16384);
            }
#pragma unroll
            for (int g = 0; g < 2; g++) {
                int row = wn + g * 16 + rA;
                uint32_t bd = stg + 32768 + row * 128 + ((slot ^ (row & 7)) << 4);
                uint32_t t0[4], t1[4];
                ldmx4(t0, bd);
                ldmx4(t1, bd + 16384);
                bh[g * 2 + 0][0] = t0[0]; bh[g * 2 + 0][1] = t0[2];
                bh[g * 2 + 1][0] = t0[1]; bh[g * 2 + 1][1] = t0[3];
                bl[g * 2 + 0][0] = t1[0]; bl[g * 2 + 0][1] = t1[2];
                bl[g * 2 + 1][0] = t1[1]; bl[g * 2 + 1][1] = t1[3];
            }
#pragma unroll
            for (int im = 0; im < 4; im++)
#pragma unroll
                for (int jn = 0; jn < 4; jn++) {
                    mma_bf16(acc[im][jn], ah[im], bh[jn]);
                    mma_bf16(acc[im][jn], ah[im], bl[jn]);
                    mma_bf16(acc[im][jn], al[im], bh[jn]);
                }
        }
        __syncthreads();   // all warps done reading stage c&1 before iter c+1 refills it
    }

    const int r0 = bm + wm + (lane >> 2);
    const int c0 = bn + wn + (lane & 3) * 2;
#pragma unroll
    for (int im = 0; im < 4; im++)
#pragma unroll
        for (int jn = 0; jn < 4; jn++) {
            float* p0 = C + (size_t)(r0 + im * 16) * N + c0 + jn * 8;
            float* p1 = C + (size_t)(r0 + im * 16 + 8) * N + c0 + jn * 8;
            *(float2*)p0 = make_float2(acc[im][jn][0], acc[im][jn][1]);
            *(float2*)p1 = make_float2(acc[im][jn][2], acc[im][jn][3]);
        }
}

__global__ void __launch_bounds__(256) qkv_mma_kernel()
{
    const int z = blockIdx.z;
    mma_gemm_body(g_xhi, g_xlo, &g_whi[z][0], &g_wlo[z][0], &g_lin[z][0]);
}

__global__ void __launch_bounds__(256) out_mma_kernel(float* __restrict__ out)
{
    mma_gemm_body(g_ahi, g_alo, &g_whi[3][0], &g_wlo[3][0], out);
}

// ---------------- RoPE + reshape to [b,h,s,dk], bf16 hi/lo output ----------------
__global__ void rope_kernel(const int* __restrict__ pos)
{
    const int z   = blockIdx.z;                         // 0=Q (rope+scale), 1=K (rope), 2=V (copy)
    const int idx = blockIdx.x * blockDim.x + threadIdx.x;
    const int j     = idx & 31;
    const int h     = (idx >> 5) & 15;
    const int chunk = (idx >> 9) & 63;
    const int b     = (idx >> 15) & 1;

    const float* src_base = &g_lin[z][0] + ((size_t)b * SEQ) * D_MODEL + h * 64 + 2 * j;
    __nv_bfloat16* dhi = (z == 0) ? g_qhi : (z == 1) ? g_khi : g_vhi;
    __nv_bfloat16* dlo = (z == 0) ? g_qlo : (z == 1) ? g_klo : g_vlo;
    const size_t dst_off = ((size_t)(b * NUM_HEADS + h) * SEQ) * D_K + 2 * j;
    const int s0 = chunk * 32;

    if (z == 2) {
        for (int ss = 0; ss < 32; ss++) {
            int s = s0 + ss;
            const float* sp = src_base + (size_t)s * D_MODEL;
            uint32_t hi, lo;
            split2(sp[0], sp[1], hi, lo);
            size_t o = dst_off + (size_t)s * D_K;
            *(uint32_t*)(dhi + o) = hi;
            *(uint32_t*)(dlo + o) = lo;
        }
    } else {
        const double freq   = exp((double)j * -0.28782313662425575);
        const double inv2pi = 0.15915494309189535;
        const double twopi  = 6.283185307179586;
        const float qscale = (z == 0) ? 0.125f : 1.0f;
        for (int ss = 0; ss < 32; ss++) {
            int s = s0 + ss;
            double ang = (double)pos[s] * freq;
            ang -= trunc(ang * inv2pi) * twopi;
            float c, sn;
            sincosf((float)ang, &sn, &c);
            const float* sp = src_base + (size_t)s * D_MODEL;
            float x1 = sp[0], x2 = sp[1];
            float r1 = (x1 * c - x2 * sn) * qscale;
            float r2 = (x1 * sn + x2 * c) * qscale;
            uint32_t hi, lo;
            split2(r1, r2, hi, lo);
            size_t o = dst_off + (size_t)s * D_K;
            *(uint32_t*)(dhi + o) = hi;
            *(uint32_t*)(dlo + o) = lo;
        }
    }
}

// ---------------- Flash attention (causal, HMMA bf16-split, 2-stage cp.async) --------
#define KH 0
#define KL 8192
#define VH 16384
#define VL 24576
#define FLASH_SMEM 65536

__global__ void __launch_bounds__(128) flash_kernel()
{
    extern __shared__ __align__(16) char fsm[];
    const uint32_t sb = smem_u32(fsm);

    const int qt = blockIdx.x;
    const int h  = blockIdx.y;
    const int bb = blockIdx.z;
    const int tid  = threadIdx.x;
    const int wid  = tid >> 5;
    const int lane = tid & 31;

    const size_t hoff = (size_t)(bb * NUM_HEADS + h) * SEQ * D_K;
    const __nv_bfloat16* Qh = g_qhi + hoff;
    const __nv_bfloat16* Ql = g_qlo + hoff;
    const __nv_bfloat16* Kh = g_khi + hoff;
    const __nv_bfloat16* Kl = g_klo + hoff;
    const __nv_bfloat16* Vh = g_vhi + hoff;
    const __nv_bfloat16* Vl = g_vlo + hoff;
    const int q0 = qt * 64;

    const int rA = (lane & 7) + 8 * ((lane >> 3) & 1);
    const int pA = (lane >> 4) & 1;

    for (int i = tid; i < 512; i += 128) {
        int r = i >> 3, ch = i & 7;
        int sw = r * 128 + ((ch ^ (r & 7)) << 4);
        size_t gix = (size_t)(q0 + r) * D_K + ch * 8;
        cp_async16(sb + 32768 + KH + sw, Qh + gix);
        cp_async16(sb + 32768 + KL + sw, Ql + gix);
    }
    CP_COMMIT();
    for (int i = tid; i < 512; i += 128) {
        int r = i >> 3, ch = i & 7;
        int sw = r * 128 + ((ch ^ (r & 7)) << 4);
        size_t gix = (size_t)r * D_K + ch * 8;
        cp_async16(sb + KH + sw, Kh + gix);
        cp_async16(sb + KL + sw, Kl + gix);
        cp_async16(sb + VH + sw, Vh + gix);
        cp_async16(sb + VL + sw, Vl + gix);
    }
    CP_COMMIT();

    CP_WAIT(1);
    __syncthreads();

    uint32_t aq[4][4], aql[4][4];
#pragma unroll
    for (int ks = 0; ks < 4; ks++) {
        int slot = ks * 2 + pA;
        int row  = wid * 16 + rA;
        uint32_t ad = sb + 32768 + KH + row * 128 + ((slot ^ (row & 7)) << 4);
        ldmx4(aq[ks], ad);
        ldmx4(aql[ks], ad + (KL - KH));
    }

    float out[8][4];
#pragma unroll
    for (int g = 0; g < 8; g++)
#pragma unroll
        for (int e = 0; e < 4; e++) out[g][e] = 0.f;
    float m0 = -1e30f, m1 = -1e30f, l0 = 0.f, l1 = 0.f;

    for (int kt = 0; kt <= qt; kt++) {
        const uint32_t sbs = sb + (uint32_t)(kt & 1) * 32768;
        CP_WAIT(0);
        __syncthreads();

        if (kt < qt) {
            const uint32_t sbn = sb + (uint32_t)((kt + 1) & 1) * 32768;
            for (int i = tid; i < 512; i += 128) {
                int r = i >> 3, ch = i & 7;
                int sw = r * 128 + ((ch ^ (r & 7)) << 4);
                size_t gix = (size_t)((kt + 1) * 64 + r) * D_K + ch * 8;
                cp_async16(sbn + KH + sw, Kh + gix);
                cp_async16(sbn + KL + sw, Kl + gix);
                cp_async16(sbn + VH + sw, Vh + gix);
                cp_async16(sbn + VL + sw, Vl + gix);
            }
            CP_COMMIT();
        }

        float s[8][4];
#pragma unroll
        for (int g = 0; g < 8; g++)
#pragma unroll
            for (int e = 0; e < 4; e++) s[g][e] = 0.f;

#pragma unroll
        for (int ks = 0; ks < 4; ks++) {
            const int slot = ks * 2 + pA;
            uint32_t bh[8][2], bl[8][2];
#pragma unroll
            for (int g2 = 0; g2 < 4; g2++) {
                int row = g2 * 16 + rA;
                uint32_t bd = sbs + KH + row * 128 + ((slot ^ (row & 7)) << 4);
                uint32_t t0[4], t1[4];
                ldmx4(t0, bd);
                ldmx4(t1, bd + (KL - KH));
                bh[g2 * 2 + 0][0] = t0[0]; bh[g2 * 2 + 0][1] = t0[2];
                bh[g2 * 2 + 1][0] = t0[1]; bh[g2 * 2 + 1][1] = t0[3];
                bl[g2 * 2 + 0][0] = t1[0]; bl[g2 * 2 + 0][1] = t1[2];
                bl[g2 * 2 + 1][0] = t1[1]; bl[g2 * 2 + 1][1] = t1[3];
            }
#pragma unroll
            for (int g = 0; g < 8; g++) {
                mma_bf16(s[g], aq[ks], bh[g]);
                mma_bf16(s[g], aq[ks], bl[g]);
                mma_bf16(s[g], aql[ks], bh[g]);
            }
        }

        if (kt == qt) {
            int r0 = wid * 16 + (lane >> 2);
#pragma unroll
            for (int g = 0; g < 8; g++) {
                int cb = 8 * g + 2 * (lane & 3);
                if (cb     > r0)     s[g][0] = -1e30f;
                if (cb + 1 > r0)     s[g][1] = -1e30f;
                if (cb     > r0 + 8) s[g][2] = -1e30f;
                if (cb + 1 > r0 + 8) s[g][3] = -1e30f;
            }
        }

        float mx0 = -1e30f, mx1 = -1e30f;
#pragma unroll
        for (int g = 0; g < 8; g++) {
            mx0 = fmaxf(mx0, fmaxf(s[g][0], s[g][1]));
            mx1 = fmaxf(mx1, fmaxf(s[g][2], s[g][3]));
        }
        mx0 = fmaxf(mx0, __shfl_xor_sync(0xffffffffu, mx0, 1));
        mx0 = fmaxf(mx0, __shfl_xor_sync(0xffffffffu, mx0, 2));
        mx1 = fmaxf(mx1, __shfl_xor_sync(0xffffffffu, mx1, 1));
        mx1 = fmaxf(mx1, __shfl_xor_sync(0xffffffffu, mx1, 2));

        float mn0 = fmaxf(m0, mx0), mn1 = fmaxf(m1, mx1);
        float sf0 = __expf(m0 - mn0), sf1 = __expf(m1 - mn1);
        m0 = mn0; m1 = mn1;

        float rs0 = 0.f, rs1 = 0.f;
#pragma unroll
        for (int g = 0; g < 8; g++) {
            s[g][0] = __expf(s[g][0] - mn0);
            s[g][1] = __expf(s[g][1] - mn0);
            s[g][2] = __expf(s[g][2] - mn1);
            s[g][3] = __expf(s[g][3] - mn1);
            rs0 += s[g][0] + s[g][1];
            rs1 += s[g][2] + s[g][3];
        }
        rs0 += __shfl_xor_sync(0xffffffffu, rs0, 1);
        rs0 += __shfl_xor_sync(0xffffffffu, rs0, 2);
        rs1 += __shfl_xor_sync(0xffffffffu, rs1, 1);
        rs1 += __shfl_xor_sync(0xffffffffu, rs1, 2);
        l0 = l0 * sf0 + rs0;
        l1 = l1 * sf1 + rs1;
#pragma unroll
        for (int g = 0; g < 8; g++) {
            out[g][0] *= sf0; out[g][1] *= sf0;
            out[g][2] *= sf1; out[g][3] *= sf1;
        }

        uint32_t ap[4][4], apl[4][4];
#pragma unroll
        for (int j = 0; j < 4; j++) {
            split2(s[2*j][0],   s[2*j][1],   ap[j][0], apl[j][0]);
            split2(s[2*j][2],   s[2*j][3],   ap[j][1], apl[j][1]);
            split2(s[2*j+1][0], s[2*j+1][1], ap[j][2], apl[j][2]);
            split2(s[2*j+1][2], s[2*j+1][3], ap[j][3], apl[j][3]);
        }

#pragma unroll
        for (int j = 0; j < 4; j++) {
            uint32_t bv[8][2], bvl[8][2];
            int krow = j * 16 + (lane & 7) + 8 * ((lane >> 3) & 1);
            int colh = (lane >> 4) & 1;
#pragma unroll
            for (int dp = 0; dp < 4; dp++) {
                int slot = dp * 2 + colh;
                uint32_t ad = sbs + VH + krow * 128 + ((slot ^ (krow & 7)) << 4);
                uint32_t t0[4], t1[4];
                ldmx4t(t0, ad);
                ldmx4t(t1, ad + (VL - VH));
                bv[dp * 2 + 0][0] = t0[0]; bv[dp * 2 + 0][1] = t0[1];
                bv[dp * 2 + 1][0] = t0[2]; bv[dp * 2 + 1][1] = t0[3];
                bvl[dp * 2 + 0][0] = t1[0]; bvl[dp * 2 + 0][1] = t1[1];
                bvl[dp * 2 + 1][0] = t1[2]; bvl[dp * 2 + 1][1] = t1[3];
            }
#pragma unroll
            for (int g = 0; g < 8; g++) {
                mma_bf16(out[g], ap[j], bv[g]);
                mma_bf16(out[g], ap[j], bvl[g]);
                mma_bf16(out[g], apl[j], bv[g]);
            }
        }
    }

    float inv0 = 1.f / l0, inv1 = 1.f / l1;
    int srow = q0 + wid * 16 + (lane >> 2);
    size_t base0 = ((size_t)(bb * SEQ) + srow) * D_MODEL + h * 64;
    size_t base1 = base0 + (size_t)8 * D_MODEL;
#pragma unroll
    for (int g = 0; g < 8; g++) {
        int d = 8 * g + 2 * (lane & 3);
        uint32_t hi, lo;
        split2(out[g][0] * inv0, out[g][1] * inv0, hi, lo);
        *(uint32_t*)(g_ahi + base0 + d) = hi;
        *(uint32_t*)(g_alo + base0 + d) = lo;
        split2(out[g][2] * inv1, out[g][3] * inv1, hi, lo);
        *(uint32_t*)(g_ahi + base1 + d) = hi;
        *(uint32_t*)(g_alo + base1 + d) = lo;
    }
}

// ---------------- launch ----------------
extern "C" void kernel_launch(void* const* d_in, const int* in_sizes, int n_in,
                              void* d_out, int out_size)
{
    const float* x   = (const float*)d_in[0];
    const int*   pos = (const int*)  d_in[1];
    const float* wq  = (const float*)d_in[2];
    const float* wk  = (const float*)d_in[3];
    const float* wv  = (const float*)d_in[4];
    const float* wo  = (const float*)d_in[5];
    float* out = (float*)d_out;

    (void)in_sizes; (void)n_in; (void)out_size;

    static bool attr_done = false;
    if (!attr_done) {
        cudaFuncSetAttribute(qkv_mma_kernel, cudaFuncAttributeMaxDynamicSharedMemorySize,
                             GEMM_SMEM);
        cudaFuncSetAttribute(out_mma_kernel, cudaFuncAttributeMaxDynamicSharedMemorySize,
                             GEMM_SMEM);
        cudaFuncSetAttribute(flash_kernel, cudaFuncAttributeMaxDynamicSharedMemorySize,
                             FLASH_SMEM);
        attr_done = true;
    }

    __nv_bfloat16 *xhi, *xlo, *whi0, *wlo0;
    cudaGetSymbolAddress((void**)&xhi,  g_xhi);
    cudaGetSymbolAddress((void**)&xlo,  g_xlo);
    cudaGetSymbolAddress((void**)&whi0, g_whi);
    cudaGetSymbolAddress((void**)&wlo0, g_wlo);

    const int n4x = M_TOK * D_MODEL / 4;
    const int n4w = D_MODEL * D_MODEL / 4;
    const size_t wsz = (size_t)D_MODEL * D_MODEL;

    cvt_split_kernel<<<(n4x + 255) / 256, 256>>>((const float4*)x, xhi, xlo, n4x);
    cvt_split_kernel<<<(n4w + 255) / 256, 256>>>((const float4*)wq, whi0, wlo0, n4w);
    cvt_split_kernel<<<(n4w + 255) / 256, 256>>>((const float4*)wk, whi0 + wsz, wlo0 + wsz, n4w);
    cvt_split_kernel<<<(n4w + 255) / 256, 256>>>((const float4*)wv, whi0 + 2 * wsz, wlo0 + 2 * wsz, n4w);
    cvt_split_kernel<<<(n4w + 255) / 256, 256>>>((const float4*)wo, whi0 + 3 * wsz, wlo0 + 3 * wsz, n4w);

    qkv_mma_kernel<<<dim3(D_MODEL / 128, M_TOK / 128, 3), 256, GEMM_SMEM>>>();
    rope_kernel<<<dim3(256, 1, 3), 256>>>(pos);
    flash_kernel<<<dim3(SEQ / 64, NUM_HEADS, BATCH), 128, FLASH_SMEM>>>();
    out_mma_kernel<<<dim3(D_MODEL / 128, M_TOK / 128, 1), 256, GEMM_SMEM>>>(out);
}

// round 10
// speedup vs baseline: 1.1218x; 1.0807x over previous
#include <cuda_runtime.h>
#include <cuda_bf16.h>
#include <math.h>
#include <stdint.h>

#define D_MODEL   1024
#define NUM_HEADS 16
#define D_K       64
#define SEQ       2048
#define BATCH     2
#define M_TOK     (BATCH*SEQ)   // 4096

// ---------------- scratch (no allocation allowed) ----------------
__device__ float g_lin[3][(size_t)M_TOK * D_MODEL];                 // QKV linear outputs (fp32)

// bf16-split operands
__device__ __nv_bfloat16 g_xhi[(size_t)M_TOK * D_MODEL];
__device__ __nv_bfloat16 g_xlo[(size_t)M_TOK * D_MODEL];
__device__ __nv_bfloat16 g_whi[4][(size_t)D_MODEL * D_MODEL];
__device__ __nv_bfloat16 g_wlo[4][(size_t)D_MODEL * D_MODEL];
__device__ __nv_bfloat16 g_ahi[(size_t)M_TOK * D_MODEL];            // attn out hi
__device__ __nv_bfloat16 g_alo[(size_t)M_TOK * D_MODEL];            // attn out lo

// roped Q/K and V, bf16 hi/lo, [b,h,s,dk]
#define HSZ ((size_t)BATCH * NUM_HEADS * SEQ * D_K)
__device__ __nv_bfloat16 g_qhi[HSZ], g_qlo[HSZ];
__device__ __nv_bfloat16 g_khi[HSZ], g_klo[HSZ];
__device__ __nv_bfloat16 g_vhi[HSZ], g_vlo[HSZ];

// ---------------- helpers ----------------
__device__ __forceinline__ uint32_t smem_u32(const void* p) {
    uint32_t a;
    asm("{ .reg .u64 t; cvta.to.shared.u64 t, %1; cvt.u32.u64 %0, t; }" : "=r"(a) : "l"(p));
    return a;
}

__device__ __forceinline__ void cp_async16(uint32_t dst, const void* src) {
    asm volatile("cp.async.cg.shared.global [%0], [%1], 16;" :: "r"(dst), "l"(src));
}
#define CP_COMMIT() asm volatile("cp.async.commit_group;" ::: "memory")
#define CP_WAIT(n)  asm volatile("cp.async.wait_group %0;" :: "n"(n) : "memory")

__device__ __forceinline__ void ldmx4(uint32_t* r, uint32_t addr) {
    asm volatile("ldmatrix.sync.aligned.m8n8.x4.shared.b16 {%0,%1,%2,%3}, [%4];"
                 : "=r"(r[0]), "=r"(r[1]), "=r"(r[2]), "=r"(r[3]) : "r"(addr));
}

__device__ __forceinline__ void ldmx4t(uint32_t* r, uint32_t addr) {
    asm volatile("ldmatrix.sync.aligned.m8n8.x4.trans.shared.b16 {%0,%1,%2,%3}, [%4];"
                 : "=r"(r[0]), "=r"(r[1]), "=r"(r[2]), "=r"(r[3]) : "r"(addr));
}

__device__ __forceinline__ void mma_bf16(float* d, const uint32_t* a, const uint32_t* b) {
    asm volatile("mma.sync.aligned.m16n8k16.row.col.f32.bf16.bf16.f32 "
                 "{%0,%1,%2,%3}, {%4,%5,%6,%7}, {%8,%9}, {%0,%1,%2,%3};"
                 : "+f"(d[0]), "+f"(d[1]), "+f"(d[2]), "+f"(d[3])
                 : "r"(a[0]), "r"(a[1]), "r"(a[2]), "r"(a[3]), "r"(b[0]), "r"(b[1]));
}

__device__ __forceinline__ void split2(float a, float b, uint32_t& hi, uint32_t& lo) {
    __nv_bfloat162 h = __floats2bfloat162_rn(a, b);
    float ra = a - __bfloat162float(h.x);
    float rb = b - __bfloat162float(h.y);
    __nv_bfloat162 l = __floats2bfloat162_rn(ra, rb);
    hi = *(uint32_t*)&h;
    lo = *(uint32_t*)&l;
}

// ---------------- split conversions: fp32 -> (bf16 hi, bf16 lo) ----------------
__global__ void cvt_split_kernel(const float4* __restrict__ src,
                                 __nv_bfloat16* __restrict__ hi,
                                 __nv_bfloat16* __restrict__ lo, int n4)
{
    int i = blockIdx.x * blockDim.x + threadIdx.x;
    if (i >= n4) return;
    float4 v = src[i];
    __nv_bfloat16 h[4], l[4];
    float f[4] = {v.x, v.y, v.z, v.w};
#pragma unroll
    for (int j = 0; j < 4; j++) {
        h[j] = __float2bfloat16(f[j]);
        l[j] = __float2bfloat16(f[j] - __bfloat162float(h[j]));
    }
    *(uint2*)&hi[(size_t)i * 4] = *(uint2*)h;
    *(uint2*)&lo[(size_t)i * 4] = *(uint2*)l;
}

// all 4 weight matrices in one launch (grid.z selects)
__global__ void cvt_w4_kernel(const float4* __restrict__ w0, const float4* __restrict__ w1,
                              const float4* __restrict__ w2, const float4* __restrict__ w3,
                              int n4)
{
    int i = blockIdx.x * blockDim.x + threadIdx.x;
    if (i >= n4) return;
    const int z = blockIdx.z;
    const float4* src = (z == 0) ? w0 : (z == 1) ? w1 : (z == 2) ? w2 : w3;
    float4 v = src[i];
    __nv_bfloat16 h[4], l[4];
    float f[4] = {v.x, v.y, v.z, v.w};
#pragma unroll
    for (int j = 0; j < 4; j++) {
        h[j] = __float2bfloat16(f[j]);
        l[j] = __float2bfloat16(f[j] - __bfloat162float(h[j]));
    }
    size_t base = (size_t)z * D_MODEL * D_MODEL + (size_t)i * 4;
    *(uint2*)&g_whi[0][base] = *(uint2*)h;
    *(uint2*)&g_wlo[0][base] = *(uint2*)l;
}

// ---------------- HMMA GEMM (R7-proven): C[M,N] = A[M,K] * W[N,K]^T -----------------
// 128x128 tile, BK=64, cp.async tile loads, single buffer, 8 warps as 2(M)x4(N).
#define GEMM_SMEM (4 * 128 * 64 * 2)

__device__ __forceinline__ void mma_gemm_body(const __nv_bfloat16* __restrict__ Ahi,
                                              const __nv_bfloat16* __restrict__ Alo,
                                              const __nv_bfloat16* __restrict__ Whi,
                                              const __nv_bfloat16* __restrict__ Wlo,
                                              float* __restrict__ C)
{
    extern __shared__ char smem[];
    const uint32_t sb = smem_u32(smem);
    const int K = D_MODEL, N = D_MODEL;
    const int bm = blockIdx.y * 128;
    const int bn = blockIdx.x * 128;
    const int tid  = threadIdx.x;
    const int wid  = tid >> 5;
    const int lane = tid & 31;
    const int wm = (wid >> 2) * 64;
    const int wn = (wid & 3) * 32;

    const __nv_bfloat16* srcs[4] = {
        Ahi + (size_t)bm * K, Alo + (size_t)bm * K,
        Whi + (size_t)bn * K, Wlo + (size_t)bn * K };

    float acc[4][4][4];
#pragma unroll
    for (int i = 0; i < 4; i++)
#pragma unroll
        for (int j = 0; j < 4; j++)
#pragma unroll
            for (int e = 0; e < 4; e++) acc[i][j][e] = 0.f;

    const int rA = (lane & 7) + ((lane >> 3) & 1) * 8;
    const int pA = (lane >> 4) & 1;

    for (int c = 0; c < 16; ++c) {
        const int k0 = c * 64;
        __syncthreads();   // all ldmatrix reads of previous chunk done
#pragma unroll
        for (int t = 0; t < 4; t++) {
            const __nv_bfloat16* S = srcs[t];
#pragma unroll
            for (int i = tid; i < 1024; i += 256) {
                int row = i >> 3, slot = i & 7;
                cp_async16(sb + t * 16384 + row * 128 + ((slot ^ (row & 7)) << 4),
                           S + (size_t)row * K + k0 + slot * 8);
            }
        }
        CP_COMMIT();
        CP_WAIT(0);
        __syncthreads();

#pragma unroll
        for (int kk = 0; kk < 4; kk++) {
            const int slot = kk * 2 + pA;
            uint32_t ah[4][4], al[4][4], bh[4][2], bl[4][2];
#pragma unroll
            for (int im = 0; im < 4; im++) {
                int row = wm + im * 16 + rA;
                uint32_t ad = sb + row * 128 + ((slot ^ (row & 7)) << 4);
                ldmx4(ah[im], ad);
                ldmx4(al[im], ad + 16384);
            }
#pragma unroll
            for (int g = 0; g < 2; g++) {
                int row = wn + g * 16 + rA;
                uint32_t bd = sb + 32768 + row * 128 + ((slot ^ (row & 7)) << 4);
                uint32_t t0[4], t1[4];
                ldmx4(t0, bd);
                ldmx4(t1, bd + 16384);
                bh[g * 2 + 0][0] = t0[0]; bh[g * 2 + 0][1] = t0[2];
                bh[g * 2 + 1][0] = t0[1]; bh[g * 2 + 1][1] = t0[3];
                bl[g * 2 + 0][0] = t1[0]; bl[g * 2 + 0][1] = t1[2];
                bl[g * 2 + 1][0] = t1[1]; bl[g * 2 + 1][1] = t1[3];
            }
#pragma unroll
            for (int im = 0; im < 4; im++)
#pragma unroll
                for (int jn = 0; jn < 4; jn++) {
                    mma_bf16(acc[im][jn], ah[im], bh[jn]);
                    mma_bf16(acc[im][jn], ah[im], bl[jn]);
                    mma_bf16(acc[im][jn], al[im], bh[jn]);
                }
        }
    }

    const int r0 = bm + wm + (lane >> 2);
    const int c0 = bn + wn + (lane & 3) * 2;
#pragma unroll
    for (int im = 0; im < 4; im++)
#pragma unroll
        for (int jn = 0; jn < 4; jn++) {
            float* p0 = C + (size_t)(r0 + im * 16) * N + c0 + jn * 8;
            float* p1 = C + (size_t)(r0 + im * 16 + 8) * N + c0 + jn * 8;
            *(float2*)p0 = make_float2(acc[im][jn][0], acc[im][jn][1]);
            *(float2*)p1 = make_float2(acc[im][jn][2], acc[im][jn][3]);
        }
}

__global__ void __launch_bounds__(256) qkv_mma_kernel()
{
    const int z = blockIdx.z;
    mma_gemm_body(g_xhi, g_xlo, &g_whi[z][0], &g_wlo[z][0], &g_lin[z][0]);
}

__global__ void __launch_bounds__(256) out_mma_kernel(float* __restrict__ out)
{
    mma_gemm_body(g_ahi, g_alo, &g_whi[3][0], &g_wlo[3][0], out);
}

// ---------------- RoPE + reshape to [b,h,s,dk], bf16 hi/lo output ----------------
__global__ void rope_kernel(const int* __restrict__ pos)
{
    const int z   = blockIdx.z;                         // 0=Q (rope+scale), 1=K (rope), 2=V (copy)
    const int idx = blockIdx.x * blockDim.x + threadIdx.x;
    const int j     = idx & 31;
    const int h     = (idx >> 5) & 15;
    const int chunk = (idx >> 9) & 63;
    const int b     = (idx >> 15) & 1;

    const float* src_base = &g_lin[z][0] + ((size_t)b * SEQ) * D_MODEL + h * 64 + 2 * j;
    __nv_bfloat16* dhi = (z == 0) ? g_qhi : (z == 1) ? g_khi : g_vhi;
    __nv_bfloat16* dlo = (z == 0) ? g_qlo : (z == 1) ? g_klo : g_vlo;
    const size_t dst_off = ((size_t)(b * NUM_HEADS + h) * SEQ) * D_K + 2 * j;
    const int s0 = chunk * 32;

    if (z == 2) {
        for (int ss = 0; ss < 32; ss++) {
            int s = s0 + ss;
            const float* sp = src_base + (size_t)s * D_MODEL;
            uint32_t hi, lo;
            split2(sp[0], sp[1], hi, lo);
            size_t o = dst_off + (size_t)s * D_K;
            *(uint32_t*)(dhi + o) = hi;
            *(uint32_t*)(dlo + o) = lo;
        }
    } else {
        const double freq   = exp((double)j * -0.28782313662425575);
        const double inv2pi = 0.15915494309189535;
        const double twopi  = 6.283185307179586;
        const float qscale = (z == 0) ? 0.125f : 1.0f;
        for (int ss = 0; ss < 32; ss++) {
            int s = s0 + ss;
            double ang = (double)pos[s] * freq;
            ang -= trunc(ang * inv2pi) * twopi;
            float c, sn;
            sincosf((float)ang, &sn, &c);
            const float* sp = src_base + (size_t)s * D_MODEL;
            float x1 = sp[0], x2 = sp[1];
            float r1 = (x1 * c - x2 * sn) * qscale;
            float r2 = (x1 * sn + x2 * c) * qscale;
            uint32_t hi, lo;
            split2(r1, r2, hi, lo);
            size_t o = dst_off + (size_t)s * D_K;
            *(uint32_t*)(dhi + o) = hi;
            *(uint32_t*)(dlo + o) = lo;
        }
    }
}

// ---------------- Flash attention (causal, HMMA bf16-split, 2-stage cp.async) --------
// Longest-first scheduling: qt = gridDim.x-1-blockIdx.x so 32-iter blocks start first.
#define KH 0
#define KL 8192
#define VH 16384
#define VL 24576
#define FLASH_SMEM 65536

__global__ void __launch_bounds__(128) flash_kernel()
{
    extern __shared__ __align__(16) char fsm[];
    const uint32_t sb = smem_u32(fsm);

    const int qt = gridDim.x - 1 - blockIdx.x;   // longest-first
    const int h  = blockIdx.y;
    const int bb = blockIdx.z;
    const int tid  = threadIdx.x;
    const int wid  = tid >> 5;
    const int lane = tid & 31;

    const size_t hoff = (size_t)(bb * NUM_HEADS + h) * SEQ * D_K;
    const __nv_bfloat16* Qh = g_qhi + hoff;
    const __nv_bfloat16* Ql = g_qlo + hoff;
    const __nv_bfloat16* Kh = g_khi + hoff;
    const __nv_bfloat16* Kl = g_klo + hoff;
    const __nv_bfloat16* Vh = g_vhi + hoff;
    const __nv_bfloat16* Vl = g_vlo + hoff;
    const int q0 = qt * 64;

    const int rA = (lane & 7) + 8 * ((lane >> 3) & 1);
    const int pA = (lane >> 4) & 1;

    for (int i = tid; i < 512; i += 128) {
        int r = i >> 3, ch = i & 7;
        int sw = r * 128 + ((ch ^ (r & 7)) << 4);
        size_t gix = (size_t)(q0 + r) * D_K + ch * 8;
        cp_async16(sb + 32768 + KH + sw, Qh + gix);
        cp_async16(sb + 32768 + KL + sw, Ql + gix);
    }
    CP_COMMIT();
    for (int i = tid; i < 512; i += 128) {
        int r = i >> 3, ch = i & 7;
        int sw = r * 128 + ((ch ^ (r & 7)) << 4);
        size_t gix = (size_t)r * D_K + ch * 8;
        cp_async16(sb + KH + sw, Kh + gix);
        cp_async16(sb + KL + sw, Kl + gix);
        cp_async16(sb + VH + sw, Vh + gix);
        cp_async16(sb + VL + sw, Vl + gix);
    }
    CP_COMMIT();

    CP_WAIT(1);
    __syncthreads();

    uint32_t aq[4][4], aql[4][4];
#pragma unroll
    for (int ks = 0; ks < 4; ks++) {
        int slot = ks * 2 + pA;
        int row  = wid * 16 + rA;
        uint32_t ad = sb + 32768 + KH + row * 128 + ((slot ^ (row & 7)) << 4);
        ldmx4(aq[ks], ad);
        ldmx4(aql[ks], ad + (KL - KH));
    }

    float out[8][4];
#pragma unroll
    for (int g = 0; g < 8; g++)
#pragma unroll
        for (int e = 0; e < 4; e++) out[g][e] = 0.f;
    float m0 = -1e30f, m1 = -1e30f, l0 = 0.f, l1 = 0.f;

    for (int kt = 0; kt <= qt; kt++) {
        const uint32_t sbs = sb + (uint32_t)(kt & 1) * 32768;
        CP_WAIT(0);
        __syncthreads();

        if (kt < qt) {
            const uint32_t sbn = sb + (uint32_t)((kt + 1) & 1) * 32768;
            for (int i = tid; i < 512; i += 128) {
                int r = i >> 3, ch = i & 7;
                int sw = r * 128 + ((ch ^ (r & 7)) << 4);
                size_t gix = (size_t)((kt + 1) * 64 + r) * D_K + ch * 8;
                cp_async16(sbn + KH + sw, Kh + gix);
                cp_async16(sbn + KL + sw, Kl + gix);
                cp_async16(sbn + VH + sw, Vh + gix);
                cp_async16(sbn + VL + sw, Vl + gix);
            }
            CP_COMMIT();
        }

        float s[8][4];
#pragma unroll
        for (int g = 0; g < 8; g++)
#pragma unroll
            for (int e = 0; e < 4; e++) s[g][e] = 0.f;

#pragma unroll
        for (int ks = 0; ks < 4; ks++) {
            const int slot = ks * 2 + pA;
            uint32_t bh[8][2], bl[8][2];
#pragma unroll
            for (int g2 = 0; g2 < 4; g2++) {
                int row = g2 * 16 + rA;
                uint32_t bd = sbs + KH + row * 128 + ((slot ^ (row & 7)) << 4);
                uint32_t t0[4], t1[4];
                ldmx4(t0, bd);
                ldmx4(t1, bd + (KL - KH));
                bh[g2 * 2 + 0][0] = t0[0]; bh[g2 * 2 + 0][1] = t0[2];
                bh[g2 * 2 + 1][0] = t0[1]; bh[g2 * 2 + 1][1] = t0[3];
                bl[g2 * 2 + 0][0] = t1[0]; bl[g2 * 2 + 0][1] = t1[2];
                bl[g2 * 2 + 1][0] = t1[1]; bl[g2 * 2 + 1][1] = t1[3];
            }
#pragma unroll
            for (int g = 0; g < 8; g++) {
                mma_bf16(s[g], aq[ks], bh[g]);
                mma_bf16(s[g], aq[ks], bl[g]);
                mma_bf16(s[g], aql[ks], bh[g]);
            }
        }

        if (kt == qt) {
            int r0 = wid * 16 + (lane >> 2);
#pragma unroll
            for (int g = 0; g < 8; g++) {
                int cb = 8 * g + 2 * (lane & 3);
                if (cb     > r0)     s[g][0] = -1e30f;
                if (cb + 1 > r0)     s[g][1] = -1e30f;
                if (cb     > r0 + 8) s[g][2] = -1e30f;
                if (cb + 1 > r0 + 8) s[g][3] = -1e30f;
            }
        }

        float mx0 = -1e30f, mx1 = -1e30f;
#pragma unroll
        for (int g = 0; g < 8; g++) {
            mx0 = fmaxf(mx0, fmaxf(s[g][0], s[g][1]));
            mx1 = fmaxf(mx1, fmaxf(s[g][2], s[g][3]));
        }
        mx0 = fmaxf(mx0, __shfl_xor_sync(0xffffffffu, mx0, 1));
        mx0 = fmaxf(mx0, __shfl_xor_sync(0xffffffffu, mx0, 2));
        mx1 = fmaxf(mx1, __shfl_xor_sync(0xffffffffu, mx1, 1));
        mx1 = fmaxf(mx1, __shfl_xor_sync(0xffffffffu, mx1, 2));

        float mn0 = fmaxf(m0, mx0), mn1 = fmaxf(m1, mx1);
        float sf0 = __expf(m0 - mn0), sf1 = __expf(m1 - mn1);
        m0 = mn0; m1 = mn1;

        float rs0 = 0.f, rs1 = 0.f;
#pragma unroll
        for (int g = 0; g < 8; g++) {
            s[g][0] = __expf(s[g][0] - mn0);
            s[g][1] = __expf(s[g][1] - mn0);
            s[g][2] = __expf(s[g][2] - mn1);
            s[g][3] = __expf(s[g][3] - mn1);
            rs0 += s[g][0] + s[g][1];
            rs1 += s[g][2] + s[g][3];
        }
        rs0 += __shfl_xor_sync(0xffffffffu, rs0, 1);
        rs0 += __shfl_xor_sync(0xffffffffu, rs0, 2);
        rs1 += __shfl_xor_sync(0xffffffffu, rs1, 1);
        rs1 += __shfl_xor_sync(0xffffffffu, rs1, 2);
        l0 = l0 * sf0 + rs0;
        l1 = l1 * sf1 + rs1;
#pragma unroll
        for (int g = 0; g < 8; g++) {
            out[g][0] *= sf0; out[g][1] *= sf0;
            out[g][2] *= sf1; out[g][3] *= sf1;
        }

        uint32_t ap[4][4], apl[4][4];
#pragma unroll
        for (int j = 0; j < 4; j++) {
            split2(s[2*j][0],   s[2*j][1],   ap[j][0], apl[j][0]);
            split2(s[2*j][2],   s[2*j][3],   ap[j][1], apl[j][1]);
            split2(s[2*j+1][0], s[2*j+1][1], ap[j][2], apl[j][2]);
            split2(s[2*j+1][2], s[2*j+1][3], ap[j][3], apl[j][3]);
        }

#pragma unroll
        for (int j = 0; j < 4; j++) {
            uint32_t bv[8][2], bvl[8][2];
            int krow = j * 16 + (lane & 7) + 8 * ((lane >> 3) & 1);
            int colh = (lane >> 4) & 1;
#pragma unroll
            for (int dp = 0; dp < 4; dp++) {
                int slot = dp * 2 + colh;
                uint32_t ad = sbs + VH + krow * 128 + ((slot ^ (krow & 7)) << 4);
                uint32_t t0[4], t1[4];
                ldmx4t(t0, ad);
                ldmx4t(t1, ad + (VL - VH));
                bv[dp * 2 + 0][0] = t0[0]; bv[dp * 2 + 0][1] = t0[1];
                bv[dp * 2 + 1][0] = t0[2]; bv[dp * 2 + 1][1] = t0[3];
                bvl[dp * 2 + 0][0] = t1[0]; bvl[dp * 2 + 0][1] = t1[1];
                bvl[dp * 2 + 1][0] = t1[2]; bvl[dp * 2 + 1][1] = t1[3];
            }
#pragma unroll
            for (int g = 0; g < 8; g++) {
                mma_bf16(out[g], ap[j], bv[g]);
                mma_bf16(out[g], ap[j], bvl[g]);
                mma_bf16(out[g], apl[j], bv[g]);
            }
        }
    }

    float inv0 = 1.f / l0, inv1 = 1.f / l1;
    int srow = q0 + wid * 16 + (lane >> 2);
    size_t base0 = ((size_t)(bb * SEQ) + srow) * D_MODEL + h * 64;
    size_t base1 = base0 + (size_t)8 * D_MODEL;
#pragma unroll
    for (int g = 0; g < 8; g++) {
        int d = 8 * g + 2 * (lane & 3);
        uint32_t hi, lo;
        split2(out[g][0] * inv0, out[g][1] * inv0, hi, lo);
        *(uint32_t*)(g_ahi + base0 + d) = hi;
        *(uint32_t*)(g_alo + base0 + d) = lo;
        split2(out[g][2] * inv1, out[g][3] * inv1, hi, lo);
        *(uint32_t*)(g_ahi + base1 + d) = hi;
        *(uint32_t*)(g_alo + base1 + d) = lo;
    }
}

// ---------------- launch ----------------
extern "C" void kernel_launch(void* const* d_in, const int* in_sizes, int n_in,
                              void* d_out, int out_size)
{
    const float* x   = (const float*)d_in[0];
    const int*   pos = (const int*)  d_in[1];
    const float* wq  = (const float*)d_in[2];
    const float* wk  = (const float*)d_in[3];
    const float* wv  = (const float*)d_in[4];
    const float* wo  = (const float*)d_in[5];
    float* out = (float*)d_out;

    (void)in_sizes; (void)n_in; (void)out_size;

    static bool attr_done = false;
    if (!attr_done) {
        cudaFuncSetAttribute(qkv_mma_kernel, cudaFuncAttributeMaxDynamicSharedMemorySize,
                             GEMM_SMEM);
        cudaFuncSetAttribute(out_mma_kernel, cudaFuncAttributeMaxDynamicSharedMemorySize,
                             GEMM_SMEM);
        cudaFuncSetAttribute(flash_kernel, cudaFuncAttributeMaxDynamicSharedMemorySize,
                             FLASH_SMEM);
        attr_done = true;
    }

    __nv_bfloat16 *xhi, *xlo;
    cudaGetSymbolAddress((void**)&xhi, g_xhi);
    cudaGetSymbolAddress((void**)&xlo, g_xlo);

    const int n4x = M_TOK * D_MODEL / 4;
    const int n4w = D_MODEL * D_MODEL / 4;

    // 0) conversions: x (1 launch) + all 4 weights (1 launch)
    cvt_split_kernel<<<(n4x + 255) / 256, 256>>>((const float4*)x, xhi, xlo, n4x);
    cvt_w4_kernel<<<dim3((n4w + 255) / 256, 1, 4), 256>>>(
        (const float4*)wq, (const float4*)wk, (const float4*)wv, (const float4*)wo, n4w);

    // 1) QKV projections (HMMA, R7-proven)
    qkv_mma_kernel<<<dim3(D_MODEL / 128, M_TOK / 128, 3), 256, GEMM_SMEM>>>();

    // 2) RoPE + reshape + bf16 split
    rope_kernel<<<dim3(256, 1, 3), 256>>>(pos);

    // 3) flash attention (HMMA, 2-stage cp.async, longest-first)
    flash_kernel<<<dim3(SEQ / 64, NUM_HEADS, BATCH), 128, FLASH_SMEM>>>();

    // 4) output projection (HMMA)
    out_mma_kernel<<<dim3(D_MODEL / 128, M_TOK / 128, 1), 256, GEMM_SMEM>>>(out);
}

// round 11
// speedup vs baseline: 1.2011x; 1.0707x over previous
#include <cuda_runtime.h>
#include <cuda_bf16.h>
#include <math.h>
#include <stdint.h>

#define D_MODEL   1024
#define NUM_HEADS 16
#define D_K       64
#define SEQ       2048
#define BATCH     2
#define M_TOK     (BATCH*SEQ)   // 4096

// ---------------- scratch (no allocation allowed) ----------------
__device__ float g_lin[3][(size_t)M_TOK * D_MODEL];                 // QKV linear outputs (fp32)

// bf16-split operands
__device__ __nv_bfloat16 g_xhi[(size_t)M_TOK * D_MODEL];
__device__ __nv_bfloat16 g_xlo[(size_t)M_TOK * D_MODEL];
__device__ __nv_bfloat16 g_whi[4][(size_t)D_MODEL * D_MODEL];
__device__ __nv_bfloat16 g_wlo[4][(size_t)D_MODEL * D_MODEL];
__device__ __nv_bfloat16 g_ahi[(size_t)M_TOK * D_MODEL];            // attn out hi
__device__ __nv_bfloat16 g_alo[(size_t)M_TOK * D_MODEL];            // attn out lo

// roped Q/K and V, bf16 hi/lo, [b,h,s,dk]
#define HSZ ((size_t)BATCH * NUM_HEADS * SEQ * D_K)
__device__ __nv_bfloat16 g_qhi[HSZ], g_qlo[HSZ];
__device__ __nv_bfloat16 g_khi[HSZ], g_klo[HSZ];
__device__ __nv_bfloat16 g_vhi[HSZ], g_vlo[HSZ];

// ---------------- helpers ----------------
__device__ __forceinline__ uint32_t smem_u32(const void* p) {
    uint32_t a;
    asm("{ .reg .u64 t; cvta.to.shared.u64 t, %1; cvt.u32.u64 %0, t; }" : "=r"(a) : "l"(p));
    return a;
}

__device__ __forceinline__ void cp_async16(uint32_t dst, const void* src) {
    asm volatile("cp.async.cg.shared.global [%0], [%1], 16;" :: "r"(dst), "l"(src));
}
#define CP_COMMIT() asm volatile("cp.async.commit_group;" ::: "memory")
#define CP_WAIT(n)  asm volatile("cp.async.wait_group %0;" :: "n"(n) : "memory")

__device__ __forceinline__ void ldmx4(uint32_t* r, uint32_t addr) {
    asm volatile("ldmatrix.sync.aligned.m8n8.x4.shared.b16 {%0,%1,%2,%3}, [%4];"
                 : "=r"(r[0]), "=r"(r[1]), "=r"(r[2]), "=r"(r[3]) : "r"(addr));
}

__device__ __forceinline__ void ldmx4t(uint32_t* r, uint32_t addr) {
    asm volatile("ldmatrix.sync.aligned.m8n8.x4.trans.shared.b16 {%0,%1,%2,%3}, [%4];"
                 : "=r"(r[0]), "=r"(r[1]), "=r"(r[2]), "=r"(r[3]) : "r"(addr));
}

__device__ __forceinline__ void mma_bf16(float* d, const uint32_t* a, const uint32_t* b) {
    asm volatile("mma.sync.aligned.m16n8k16.row.col.f32.bf16.bf16.f32 "
                 "{%0,%1,%2,%3}, {%4,%5,%6,%7}, {%8,%9}, {%0,%1,%2,%3};"
                 : "+f"(d[0]), "+f"(d[1]), "+f"(d[2]), "+f"(d[3])
                 : "r"(a[0]), "r"(a[1]), "r"(a[2]), "r"(a[3]), "r"(b[0]), "r"(b[1]));
}

__device__ __forceinline__ void split2(float a, float b, uint32_t& hi, uint32_t& lo) {
    __nv_bfloat162 h = __floats2bfloat162_rn(a, b);
    float ra = a - __bfloat162float(h.x);
    float rb = b - __bfloat162float(h.y);
    __nv_bfloat162 l = __floats2bfloat162_rn(ra, rb);
    hi = *(uint32_t*)&h;
    lo = *(uint32_t*)&l;
}

// ---------------- split conversions: fp32 -> (bf16 hi, bf16 lo) ----------------
__global__ void cvt_split_kernel(const float4* __restrict__ src,
                                 __nv_bfloat16* __restrict__ hi,
                                 __nv_bfloat16* __restrict__ lo, int n4)
{
    int i = blockIdx.x * blockDim.x + threadIdx.x;
    if (i >= n4) return;
    float4 v = src[i];
    __nv_bfloat16 h[4], l[4];
    float f[4] = {v.x, v.y, v.z, v.w};
#pragma unroll
    for (int j = 0; j < 4; j++) {
        h[j] = __float2bfloat16(f[j]);
        l[j] = __float2bfloat16(f[j] - __bfloat162float(h[j]));
    }
    *(uint2*)&hi[(size_t)i * 4] = *(uint2*)h;
    *(uint2*)&lo[(size_t)i * 4] = *(uint2*)l;
}

// all 4 weight matrices in one launch (grid.z selects)
__global__ void cvt_w4_kernel(const float4* __restrict__ w0, const float4* __restrict__ w1,
                              const float4* __restrict__ w2, const float4* __restrict__ w3,
                              int n4)
{
    int i = blockIdx.x * blockDim.x + threadIdx.x;
    if (i >= n4) return;
    const int z = blockIdx.z;
    const float4* src = (z == 0) ? w0 : (z == 1) ? w1 : (z == 2) ? w2 : w3;
    float4 v = src[i];
    __nv_bfloat16 h[4], l[4];
    float f[4] = {v.x, v.y, v.z, v.w};
#pragma unroll
    for (int j = 0; j < 4; j++) {
        h[j] = __float2bfloat16(f[j]);
        l[j] = __float2bfloat16(f[j] - __bfloat162float(h[j]));
    }
    size_t base = (size_t)z * D_MODEL * D_MODEL + (size_t)i * 4;
    *(uint2*)&g_whi[0][base] = *(uint2*)h;
    *(uint2*)&g_wlo[0][base] = *(uint2*)l;
}

// ---------------- HMMA GEMM (R7-proven): C[M,N] = A[M,K] * W[N,K]^T -----------------
#define GEMM_SMEM (4 * 128 * 64 * 2)

__device__ __forceinline__ void mma_gemm_body(const __nv_bfloat16* __restrict__ Ahi,
                                              const __nv_bfloat16* __restrict__ Alo,
                                              const __nv_bfloat16* __restrict__ Whi,
                                              const __nv_bfloat16* __restrict__ Wlo,
                                              float* __restrict__ C)
{
    extern __shared__ char smem[];
    const uint32_t sb = smem_u32(smem);
    const int K = D_MODEL, N = D_MODEL;
    const int bm = blockIdx.y * 128;
    const int bn = blockIdx.x * 128;
    const int tid  = threadIdx.x;
    const int wid  = tid >> 5;
    const int lane = tid & 31;
    const int wm = (wid >> 2) * 64;
    const int wn = (wid & 3) * 32;

    const __nv_bfloat16* srcs[4] = {
        Ahi + (size_t)bm * K, Alo + (size_t)bm * K,
        Whi + (size_t)bn * K, Wlo + (size_t)bn * K };

    float acc[4][4][4];
#pragma unroll
    for (int i = 0; i < 4; i++)
#pragma unroll
        for (int j = 0; j < 4; j++)
#pragma unroll
            for (int e = 0; e < 4; e++) acc[i][j][e] = 0.f;

    const int rA = (lane & 7) + ((lane >> 3) & 1) * 8;
    const int pA = (lane >> 4) & 1;

    for (int c = 0; c < 16; ++c) {
        const int k0 = c * 64;
        __syncthreads();
#pragma unroll
        for (int t = 0; t < 4; t++) {
            const __nv_bfloat16* S = srcs[t];
#pragma unroll
            for (int i = tid; i < 1024; i += 256) {
                int row = i >> 3, slot = i & 7;
                cp_async16(sb + t * 16384 + row * 128 + ((slot ^ (row & 7)) << 4),
                           S + (size_t)row * K + k0 + slot * 8);
            }
        }
        CP_COMMIT();
        CP_WAIT(0);
        __syncthreads();

#pragma unroll
        for (int kk = 0; kk < 4; kk++) {
            const int slot = kk * 2 + pA;
            uint32_t ah[4][4], al[4][4], bh[4][2], bl[4][2];
#pragma unroll
            for (int im = 0; im < 4; im++) {
                int row = wm + im * 16 + rA;
                uint32_t ad = sb + row * 128 + ((slot ^ (row & 7)) << 4);
                ldmx4(ah[im], ad);
                ldmx4(al[im], ad + 16384);
            }
#pragma unroll
            for (int g = 0; g < 2; g++) {
                int row = wn + g * 16 + rA;
                uint32_t bd = sb + 32768 + row * 128 + ((slot ^ (row & 7)) << 4);
                uint32_t t0[4], t1[4];
                ldmx4(t0, bd);
                ldmx4(t1, bd + 16384);
                bh[g * 2 + 0][0] = t0[0]; bh[g * 2 + 0][1] = t0[2];
                bh[g * 2 + 1][0] = t0[1]; bh[g * 2 + 1][1] = t0[3];
                bl[g * 2 + 0][0] = t1[0]; bl[g * 2 + 0][1] = t1[2];
                bl[g * 2 + 1][0] = t1[1]; bl[g * 2 + 1][1] = t1[3];
            }
#pragma unroll
            for (int im = 0; im < 4; im++)
#pragma unroll
                for (int jn = 0; jn < 4; jn++) {
                    mma_bf16(acc[im][jn], ah[im], bh[jn]);
                    mma_bf16(acc[im][jn], ah[im], bl[jn]);
                    mma_bf16(acc[im][jn], al[im], bh[jn]);
                }
        }
    }

    const int r0 = bm + wm + (lane >> 2);
    const int c0 = bn + wn + (lane & 3) * 2;
#pragma unroll
    for (int im = 0; im < 4; im++)
#pragma unroll
        for (int jn = 0; jn < 4; jn++) {
            float* p0 = C + (size_t)(r0 + im * 16) * N + c0 + jn * 8;
            float* p1 = C + (size_t)(r0 + im * 16 + 8) * N + c0 + jn * 8;
            *(float2*)p0 = make_float2(acc[im][jn][0], acc[im][jn][1]);
            *(float2*)p1 = make_float2(acc[im][jn][2], acc[im][jn][3]);
        }
}

__global__ void __launch_bounds__(256) qkv_mma_kernel()
{
    const int z = blockIdx.z;
    mma_gemm_body(g_xhi, g_xlo, &g_whi[z][0], &g_wlo[z][0], &g_lin[z][0]);
}

__global__ void __launch_bounds__(256) out_mma_kernel(float* __restrict__ out)
{
    mma_gemm_body(g_ahi, g_alo, &g_whi[3][0], &g_wlo[3][0], out);
}

// ---------------- RoPE + reshape to [b,h,s,dk], bf16 hi/lo output ----------------
// z=0: Q+K fused (one sincos per (s,j), fp32 angles matching reference rounding).
// z=1: V copy. No fp64 in inner loops.
__global__ void rope_kernel(const int* __restrict__ pos)
{
    const int z   = blockIdx.z;
    const int idx = blockIdx.x * blockDim.x + threadIdx.x;
    const int j     = idx & 31;
    const int h     = (idx >> 5) & 15;
    const int chunk = (idx >> 9) & 63;
    const int b     = (idx >> 15) & 1;

    const size_t src_off = ((size_t)b * SEQ) * D_MODEL + h * 64 + 2 * j;
    const size_t dst_off = ((size_t)(b * NUM_HEADS + h) * SEQ) * D_K + 2 * j;
    const int s0 = chunk * 32;

    if (z == 1) {
        const float* sv = &g_lin[2][0] + src_off;
        for (int ss = 0; ss < 32; ss++) {
            int s = s0 + ss;
            const float* sp = sv + (size_t)s * D_MODEL;
            uint32_t hi, lo;
            split2(sp[0], sp[1], hi, lo);
            size_t o = dst_off + (size_t)s * D_K;
            *(uint32_t*)(g_vhi + o) = hi;
            *(uint32_t*)(g_vlo + o) = lo;
        }
    } else {
        // freq computed once in double, correctly rounded to fp32 (matches reference's
        // fp32 freqs); per-s angle is an fp32 product — the same rounding the
        // reference applies (positions_f32 * freqs_f32).
        const float freqf = (float)exp((double)j * -0.28782313662425575);
        const float* sq = &g_lin[0][0] + src_off;
        const float* sk = &g_lin[1][0] + src_off;
        for (int ss = 0; ss < 32; ss++) {
            int s = s0 + ss;
            float ang = (float)pos[s] * freqf;
            float c, sn;
            sincosf(ang, &sn, &c);
            size_t o = dst_off + (size_t)s * D_K;

            const float* qp = sq + (size_t)s * D_MODEL;
            float q1 = qp[0], q2 = qp[1];
            uint32_t hi, lo;
            split2((q1 * c - q2 * sn) * 0.125f, (q1 * sn + q2 * c) * 0.125f, hi, lo);
            *(uint32_t*)(g_qhi + o) = hi;
            *(uint32_t*)(g_qlo + o) = lo;

            const float* kp = sk + (size_t)s * D_MODEL;
            float k1 = kp[0], k2 = kp[1];
            split2(k1 * c - k2 * sn, k1 * sn + k2 * c, hi, lo);
            *(uint32_t*)(g_khi + o) = hi;
            *(uint32_t*)(g_klo + o) = lo;
        }
    }
}

// ---------------- Flash attention (causal, HMMA bf16-split, 2-stage cp.async) --------
// Longest-first scheduling: qt = gridDim.x-1-blockIdx.x.
#define KH 0
#define KL 8192
#define VH 16384
#define VL 24576
#define FLASH_SMEM 65536

__global__ void __launch_bounds__(128) flash_kernel()
{
    extern __shared__ __align__(16) char fsm[];
    const uint32_t sb = smem_u32(fsm);

    const int qt = gridDim.x - 1 - blockIdx.x;   // longest-first
    const int h  = blockIdx.y;
    const int bb = blockIdx.z;
    const int tid  = threadIdx.x;
    const int wid  = tid >> 5;
    const int lane = tid & 31;

    const size_t hoff = (size_t)(bb * NUM_HEADS + h) * SEQ * D_K;
    const __nv_bfloat16* Qh = g_qhi + hoff;
    const __nv_bfloat16* Ql = g_qlo + hoff;
    const __nv_bfloat16* Kh = g_khi + hoff;
    const __nv_bfloat16* Kl = g_klo + hoff;
    const __nv_bfloat16* Vh = g_vhi + hoff;
    const __nv_bfloat16* Vl = g_vlo + hoff;
    const int q0 = qt * 64;

    const int rA = (lane & 7) + 8 * ((lane >> 3) & 1);
    const int pA = (lane >> 4) & 1;

    for (int i = tid; i < 512; i += 128) {
        int r = i >> 3, ch = i & 7;
        int sw = r * 128 + ((ch ^ (r & 7)) << 4);
        size_t gix = (size_t)(q0 + r) * D_K + ch * 8;
        cp_async16(sb + 32768 + KH + sw, Qh + gix);
        cp_async16(sb + 32768 + KL + sw, Ql + gix);
    }
    CP_COMMIT();
    for (int i = tid; i < 512; i += 128) {
        int r = i >> 3, ch = i & 7;
        int sw = r * 128 + ((ch ^ (r & 7)) << 4);
        size_t gix = (size_t)r * D_K + ch * 8;
        cp_async16(sb + KH + sw, Kh + gix);
        cp_async16(sb + KL + sw, Kl + gix);
        cp_async16(sb + VH + sw, Vh + gix);
        cp_async16(sb + VL + sw, Vl + gix);
    }
    CP_COMMIT();

    CP_WAIT(1);
    __syncthreads();

    uint32_t aq[4][4], aql[4][4];
#pragma unroll
    for (int ks = 0; ks < 4; ks++) {
        int slot = ks * 2 + pA;
        int row  = wid * 16 + rA;
        uint32_t ad = sb + 32768 + KH + row * 128 + ((slot ^ (row & 7)) << 4);
        ldmx4(aq[ks], ad);
        ldmx4(aql[ks], ad + (KL - KH));
    }

    float out[8][4];
#pragma unroll
    for (int g = 0; g < 8; g++)
#pragma unroll
        for (int e = 0; e < 4; e++) out[g][e] = 0.f;
    float m0 = -1e30f, m1 = -1e30f, l0 = 0.f, l1 = 0.f;

    for (int kt = 0; kt <= qt; kt++) {
        const uint32_t sbs = sb + (uint32_t)(kt & 1) * 32768;
        CP_WAIT(0);
        __syncthreads();

        if (kt < qt) {
            const uint32_t sbn = sb + (uint32_t)((kt + 1) & 1) * 32768;
            for (int i = tid; i < 512; i += 128) {
                int r = i >> 3, ch = i & 7;
                int sw = r * 128 + ((ch ^ (r & 7)) << 4);
                size_t gix = (size_t)((kt + 1) * 64 + r) * D_K + ch * 8;
                cp_async16(sbn + KH + sw, Kh + gix);
                cp_async16(sbn + KL + sw, Kl + gix);
                cp_async16(sbn + VH + sw, Vh + gix);
                cp_async16(sbn + VL + sw, Vl + gix);
            }
            CP_COMMIT();
        }

        float s[8][4];
#pragma unroll
        for (int g = 0; g < 8; g++)
#pragma unroll
            for (int e = 0; e < 4; e++) s[g][e] = 0.f;

#pragma unroll
        for (int ks = 0; ks < 4; ks++) {
            const int slot = ks * 2 + pA;
            uint32_t bh[8][2], bl[8][2];
#pragma unroll
            for (int g2 = 0; g2 < 4; g2++) {
                int row = g2 * 16 + rA;
                uint32_t bd = sbs + KH + row * 128 + ((slot ^ (row & 7)) << 4);
                uint32_t t0[4], t1[4];
                ldmx4(t0, bd);
                ldmx4(t1, bd + (KL - KH));
                bh[g2 * 2 + 0][0] = t0[0]; bh[g2 * 2 + 0][1] = t0[2];
                bh[g2 * 2 + 1][0] = t0[1]; bh[g2 * 2 + 1][1] = t0[3];
                bl[g2 * 2 + 0][0] = t1[0]; bl[g2 * 2 + 0][1] = t1[2];
                bl[g2 * 2 + 1][0] = t1[1]; bl[g2 * 2 + 1][1] = t1[3];
            }
#pragma unroll
            for (int g = 0; g < 8; g++) {
                mma_bf16(s[g], aq[ks], bh[g]);
                mma_bf16(s[g], aq[ks], bl[g]);
                mma_bf16(s[g], aql[ks], bh[g]);
            }
        }

        if (kt == qt) {
            int r0 = wid * 16 + (lane >> 2);
#pragma unroll
            for (int g = 0; g < 8; g++) {
                int cb = 8 * g + 2 * (lane & 3);
                if (cb     > r0)     s[g][0] = -1e30f;
                if (cb + 1 > r0)     s[g][1] = -1e30f;
                if (cb     > r0 + 8) s[g][2] = -1e30f;
                if (cb + 1 > r0 + 8) s[g][3] = -1e30f;
            }
        }

        float mx0 = -1e30f, mx1 = -1e30f;
#pragma unroll
        for (int g = 0; g < 8; g++) {
            mx0 = fmaxf(mx0, fmaxf(s[g][0], s[g][1]));
            mx1 = fmaxf(mx1, fmaxf(s[g][2], s[g][3]));
        }
        mx0 = fmaxf(mx0, __shfl_xor_sync(0xffffffffu, mx0, 1));
        mx0 = fmaxf(mx0, __shfl_xor_sync(0xffffffffu, mx0, 2));
        mx1 = fmaxf(mx1, __shfl_xor_sync(0xffffffffu, mx1, 1));
        mx1 = fmaxf(mx1, __shfl_xor_sync(0xffffffffu, mx1, 2));

        float mn0 = fmaxf(m0, mx0), mn1 = fmaxf(m1, mx1);
        float sf0 = __expf(m0 - mn0), sf1 = __expf(m1 - mn1);
        m0 = mn0; m1 = mn1;

        float rs0 = 0.f, rs1 = 0.f;
#pragma unroll
        for (int g = 0; g < 8; g++) {
            s[g][0] = __expf(s[g][0] - mn0);
            s[g][1] = __expf(s[g][1] - mn0);
            s[g][2] = __expf(s[g][2] - mn1);
            s[g][3] = __expf(s[g][3] - mn1);
            rs0 += s[g][0] + s[g][1];
            rs1 += s[g][2] + s[g][3];
        }
        rs0 += __shfl_xor_sync(0xffffffffu, rs0, 1);
        rs0 += __shfl_xor_sync(0xffffffffu, rs0, 2);
        rs1 += __shfl_xor_sync(0xffffffffu, rs1, 1);
        rs1 += __shfl_xor_sync(0xffffffffu, rs1, 2);
        l0 = l0 * sf0 + rs0;
        l1 = l1 * sf1 + rs1;
#pragma unroll
        for (int g = 0; g < 8; g++) {
            out[g][0] *= sf0; out[g][1] *= sf0;
            out[g][2] *= sf1; out[g][3] *= sf1;
        }

        uint32_t ap[4][4], apl[4][4];
#pragma unroll
        for (int j = 0; j < 4; j++) {
            split2(s[2*j][0],   s[2*j][1],   ap[j][0], apl[j][0]);
            split2(s[2*j][2],   s[2*j][3],   ap[j][1], apl[j][1]);
            split2(s[2*j+1][0], s[2*j+1][1], ap[j][2], apl[j][2]);
            split2(s[2*j+1][2], s[2*j+1][3], ap[j][3], apl[j][3]);
        }

#pragma unroll
        for (int j = 0; j < 4; j++) {
            uint32_t bv[8][2], bvl[8][2];
            int krow = j * 16 + (lane & 7) + 8 * ((lane >> 3) & 1);
            int colh = (lane >> 4) & 1;
#pragma unroll
            for (int dp = 0; dp < 4; dp++) {
                int slot = dp * 2 + colh;
                uint32_t ad = sbs + VH + krow * 128 + ((slot ^ (krow & 7)) << 4);
                uint32_t t0[4], t1[4];
                ldmx4t(t0, ad);
                ldmx4t(t1, ad + (VL - VH));
                bv[dp * 2 + 0][0] = t0[0]; bv[dp * 2 + 0][1] = t0[1];
                bv[dp * 2 + 1][0] = t0[2]; bv[dp * 2 + 1][1] = t0[3];
                bvl[dp * 2 + 0][0] = t1[0]; bvl[dp * 2 + 0][1] = t1[1];
                bvl[dp * 2 + 1][0] = t1[2]; bvl[dp * 2 + 1][1] = t1[3];
            }
#pragma unroll
            for (int g = 0; g < 8; g++) {
                mma_bf16(out[g], ap[j], bv[g]);
                mma_bf16(out[g], ap[j], bvl[g]);
                mma_bf16(out[g], apl[j], bv[g]);
            }
        }
    }

    float inv0 = 1.f / l0, inv1 = 1.f / l1;
    int srow = q0 + wid * 16 + (lane >> 2);
    size_t base0 = ((size_t)(bb * SEQ) + srow) * D_MODEL + h * 64;
    size_t base1 = base0 + (size_t)8 * D_MODEL;
#pragma unroll
    for (int g = 0; g < 8; g++) {
        int d = 8 * g + 2 * (lane & 3);
        uint32_t hi, lo;
        split2(out[g][0] * inv0, out[g][1] * inv0, hi, lo);
        *(uint32_t*)(g_ahi + base0 + d) = hi;
        *(uint32_t*)(g_alo + base0 + d) = lo;
        split2(out[g][2] * inv1, out[g][3] * inv1, hi, lo);
        *(uint32_t*)(g_ahi + base1 + d) = hi;
        *(uint32_t*)(g_alo + base1 + d) = lo;
    }
}

// ---------------- launch ----------------
extern "C" void kernel_launch(void* const* d_in, const int* in_sizes, int n_in,
                              void* d_out, int out_size)
{
    const float* x   = (const float*)d_in[0];
    const int*   pos = (const int*)  d_in[1];
    const float* wq  = (const float*)d_in[2];
    const float* wk  = (const float*)d_in[3];
    const float* wv  = (const float*)d_in[4];
    const float* wo  = (const float*)d_in[5];
    float* out = (float*)d_out;

    (void)in_sizes; (void)n_in; (void)out_size;

    static bool attr_done = false;
    if (!attr_done) {
        cudaFuncSetAttribute(qkv_mma_kernel, cudaFuncAttributeMaxDynamicSharedMemorySize,
                             GEMM_SMEM);
        cudaFuncSetAttribute(out_mma_kernel, cudaFuncAttributeMaxDynamicSharedMemorySize,
                             GEMM_SMEM);
        cudaFuncSetAttribute(flash_kernel, cudaFuncAttributeMaxDynamicSharedMemorySize,
                             FLASH_SMEM);
        attr_done = true;
    }

    __nv_bfloat16 *xhi, *xlo;
    cudaGetSymbolAddress((void**)&xhi, g_xhi);
    cudaGetSymbolAddress((void**)&xlo, g_xlo);

    const int n4x = M_TOK * D_MODEL / 4;
    const int n4w = D_MODEL * D_MODEL / 4;

    // 0) conversions: x (1 launch) + all 4 weights (1 launch)
    cvt_split_kernel<<<(n4x + 255) / 256, 256>>>((const float4*)x, xhi, xlo, n4x);
    cvt_w4_kernel<<<dim3((n4w + 255) / 256, 1, 4), 256>>>(
        (const float4*)wq, (const float4*)wk, (const float4*)wv, (const float4*)wo, n4w);

    // 1) QKV projections (HMMA)
    qkv_mma_kernel<<<dim3(D_MODEL / 128, M_TOK / 128, 3), 256, GEMM_SMEM>>>();

    // 2) RoPE (Q+K fused, fp32 angles) + V copy + bf16 split
    rope_kernel<<<dim3(256, 1, 2), 256>>>(pos);

    // 3) flash attention (HMMA, 2-stage cp.async, longest-first)
    flash_kernel<<<dim3(SEQ / 64, NUM_HEADS, BATCH), 128, FLASH_SMEM>>>();

    // 4) output projection (HMMA)
    out_mma_kernel<<<dim3(D_MODEL / 128, M_TOK / 128, 1), 256, GEMM_SMEM>>>(out);
}

// round 12
// speedup vs baseline: 1.3135x; 1.0936x over previous
#include <cuda_runtime.h>
#include <cuda_bf16.h>
#include <math.h>
#include <stdint.h>

#define D_MODEL   1024
#define NUM_HEADS 16
#define D_K       64
#define SEQ       2048
#define BATCH     2
#define M_TOK     (BATCH*SEQ)   // 4096

// ---------------- scratch (no allocation allowed) ----------------
// bf16-split operands
__device__ __nv_bfloat16 g_xhi[(size_t)M_TOK * D_MODEL];
__device__ __nv_bfloat16 g_xlo[(size_t)M_TOK * D_MODEL];
__device__ __nv_bfloat16 g_whi[4][(size_t)D_MODEL * D_MODEL];
__device__ __nv_bfloat16 g_wlo[4][(size_t)D_MODEL * D_MODEL];
__device__ __nv_bfloat16 g_ahi[(size_t)M_TOK * D_MODEL];            // attn out hi
__device__ __nv_bfloat16 g_alo[(size_t)M_TOK * D_MODEL];            // attn out lo

// roped Q/K and V, bf16 hi/lo, [b,h,s,dk]
#define HSZ ((size_t)BATCH * NUM_HEADS * SEQ * D_K)
__device__ __nv_bfloat16 g_qhi[HSZ], g_qlo[HSZ];
__device__ __nv_bfloat16 g_khi[HSZ], g_klo[HSZ];
__device__ __nv_bfloat16 g_vhi[HSZ], g_vlo[HSZ];

// ---------------- helpers ----------------
__device__ __forceinline__ uint32_t smem_u32(const void* p) {
    uint32_t a;
    asm("{ .reg .u64 t; cvta.to.shared.u64 t, %1; cvt.u32.u64 %0, t; }" : "=r"(a) : "l"(p));
    return a;
}

__device__ __forceinline__ void cp_async16(uint32_t dst, const void* src) {
    asm volatile("cp.async.cg.shared.global [%0], [%1], 16;" :: "r"(dst), "l"(src));
}
#define CP_COMMIT() asm volatile("cp.async.commit_group;" ::: "memory")
#define CP_WAIT(n)  asm volatile("cp.async.wait_group %0;" :: "n"(n) : "memory")

__device__ __forceinline__ void ldmx4(uint32_t* r, uint32_t addr) {
    asm volatile("ldmatrix.sync.aligned.m8n8.x4.shared.b16 {%0,%1,%2,%3}, [%4];"
                 : "=r"(r[0]), "=r"(r[1]), "=r"(r[2]), "=r"(r[3]) : "r"(addr));
}

__device__ __forceinline__ void ldmx4t(uint32_t* r, uint32_t addr) {
    asm volatile("ldmatrix.sync.aligned.m8n8.x4.trans.shared.b16 {%0,%1,%2,%3}, [%4];"
                 : "=r"(r[0]), "=r"(r[1]), "=r"(r[2]), "=r"(r[3]) : "r"(addr));
}

__device__ __forceinline__ void mma_bf16(float* d, const uint32_t* a, const uint32_t* b) {
    asm volatile("mma.sync.aligned.m16n8k16.row.col.f32.bf16.bf16.f32 "
                 "{%0,%1,%2,%3}, {%4,%5,%6,%7}, {%8,%9}, {%0,%1,%2,%3};"
                 : "+f"(d[0]), "+f"(d[1]), "+f"(d[2]), "+f"(d[3])
                 : "r"(a[0]), "r"(a[1]), "r"(a[2]), "r"(a[3]), "r"(b[0]), "r"(b[1]));
}

__device__ __forceinline__ void split2(float a, float b, uint32_t& hi, uint32_t& lo) {
    __nv_bfloat162 h = __floats2bfloat162_rn(a, b);
    float ra = a - __bfloat162float(h.x);
    float rb = b - __bfloat162float(h.y);
    __nv_bfloat162 l = __floats2bfloat162_rn(ra, rb);
    hi = *(uint32_t*)&h;
    lo = *(uint32_t*)&l;
}

// ---------------- split conversions: fp32 -> (bf16 hi, bf16 lo) ----------------
__global__ void cvt_split_kernel(const float4* __restrict__ src,
                                 __nv_bfloat16* __restrict__ hi,
                                 __nv_bfloat16* __restrict__ lo, int n4)
{
    int i = blockIdx.x * blockDim.x + threadIdx.x;
    if (i >= n4) return;
    float4 v = src[i];
    __nv_bfloat16 h[4], l[4];
    float f[4] = {v.x, v.y, v.z, v.w};
#pragma unroll
    for (int j = 0; j < 4; j++) {
        h[j] = __float2bfloat16(f[j]);
        l[j] = __float2bfloat16(f[j] - __bfloat162float(h[j]));
    }
    *(uint2*)&hi[(size_t)i * 4] = *(uint2*)h;
    *(uint2*)&lo[(size_t)i * 4] = *(uint2*)l;
}

// all 4 weight matrices in one launch (grid.z selects)
__global__ void cvt_w4_kernel(const float4* __restrict__ w0, const float4* __restrict__ w1,
                              const float4* __restrict__ w2, const float4* __restrict__ w3,
                              int n4)
{
    int i = blockIdx.x * blockDim.x + threadIdx.x;
    if (i >= n4) return;
    const int z = blockIdx.z;
    const float4* src = (z == 0) ? w0 : (z == 1) ? w1 : (z == 2) ? w2 : w3;
    float4 v = src[i];
    __nv_bfloat16 h[4], l[4];
    float f[4] = {v.x, v.y, v.z, v.w};
#pragma unroll
    for (int j = 0; j < 4; j++) {
        h[j] = __float2bfloat16(f[j]);
        l[j] = __float2bfloat16(f[j] - __bfloat162float(h[j]));
    }
    size_t base = (size_t)z * D_MODEL * D_MODEL + (size_t)i * 4;
    *(uint2*)&g_whi[0][base] = *(uint2*)h;
    *(uint2*)&g_wlo[0][base] = *(uint2*)l;
}

// ---------------- HMMA GEMM mainloop (R7-proven): acc = A[M,K] * W[N,K]^T -----------
// 128x128 tile, BK=64, cp.async tile loads, single buffer, 8 warps as 2(M)x4(N).
#define GEMM_SMEM (4 * 128 * 64 * 2)

__device__ __forceinline__ void mma_mainloop(const __nv_bfloat16* __restrict__ Ahi,
                                             const __nv_bfloat16* __restrict__ Alo,
                                             const __nv_bfloat16* __restrict__ Whi,
                                             const __nv_bfloat16* __restrict__ Wlo,
                                             float acc[4][4][4],
                                             uint32_t sb, int bm, int bn,
                                             int tid, int wm, int wn, int lane)
{
    const int K = D_MODEL;
    const __nv_bfloat16* srcs[4] = {
        Ahi + (size_t)bm * K, Alo + (size_t)bm * K,
        Whi + (size_t)bn * K, Wlo + (size_t)bn * K };

#pragma unroll
    for (int i = 0; i < 4; i++)
#pragma unroll
        for (int j = 0; j < 4; j++)
#pragma unroll
            for (int e = 0; e < 4; e++) acc[i][j][e] = 0.f;

    const int rA = (lane & 7) + ((lane >> 3) & 1) * 8;
    const int pA = (lane >> 4) & 1;

    for (int c = 0; c < 16; ++c) {
        const int k0 = c * 64;
        __syncthreads();
#pragma unroll
        for (int t = 0; t < 4; t++) {
            const __nv_bfloat16* S = srcs[t];
#pragma unroll
            for (int i = tid; i < 1024; i += 256) {
                int row = i >> 3, slot = i & 7;
                cp_async16(sb + t * 16384 + row * 128 + ((slot ^ (row & 7)) << 4),
                           S + (size_t)row * K + k0 + slot * 8);
            }
        }
        CP_COMMIT();
        CP_WAIT(0);
        __syncthreads();

#pragma unroll
        for (int kk = 0; kk < 4; kk++) {
            const int slot = kk * 2 + pA;
            uint32_t ah[4][4], al[4][4], bh[4][2], bl[4][2];
#pragma unroll
            for (int im = 0; im < 4; im++) {
                int row = wm + im * 16 + rA;
                uint32_t ad = sb + row * 128 + ((slot ^ (row & 7)) << 4);
                ldmx4(ah[im], ad);
                ldmx4(al[im], ad + 16384);
            }
#pragma unroll
            for (int g = 0; g < 2; g++) {
                int row = wn + g * 16 + rA;
                uint32_t bd = sb + 32768 + row * 128 + ((slot ^ (row & 7)) << 4);
                uint32_t t0[4], t1[4];
                ldmx4(t0, bd);
                ldmx4(t1, bd + 16384);
                bh[g * 2 + 0][0] = t0[0]; bh[g * 2 + 0][1] = t0[2];
                bh[g * 2 + 1][0] = t0[1]; bh[g * 2 + 1][1] = t0[3];
                bl[g * 2 + 0][0] = t1[0]; bl[g * 2 + 0][1] = t1[2];
                bl[g * 2 + 1][0] = t1[1]; bl[g * 2 + 1][1] = t1[3];
            }
#pragma unroll
            for (int im = 0; im < 4; im++)
#pragma unroll
                for (int jn = 0; jn < 4; jn++) {
                    mma_bf16(acc[im][jn], ah[im], bh[jn]);
                    mma_bf16(acc[im][jn], ah[im], bl[jn]);
                    mma_bf16(acc[im][jn], al[im], bh[jn]);
                }
        }
    }
}

// QKV projection with fused RoPE + bf16-split epilogue (z: 0=Q,1=K,2=V).
__global__ void __launch_bounds__(256) qkv_mma_kernel(const int* __restrict__ pos)
{
    extern __shared__ char smem[];
    const uint32_t sb = smem_u32(smem);
    const int z = blockIdx.z;
    const int bm = blockIdx.y * 128;
    const int bn = blockIdx.x * 128;
    const int tid  = threadIdx.x;
    const int wid  = tid >> 5;
    const int lane = tid & 31;
    const int wm = (wid >> 2) * 64;
    const int wn = (wid & 3) * 32;

    float acc[4][4][4];
    mma_mainloop(g_xhi, g_xlo, &g_whi[z][0], &g_wlo[z][0], acc,
                 sb, bm, bn, tid, wm, wn, lane);

    // epilogue: rows r0+im*16 (+8) are tokens; cols c0+jn*8 (+1) are (h*64+d) pairs.
    const int r0 = bm + wm + (lane >> 2);
    const int c0 = bn + wn + (lane & 3) * 2;

    __nv_bfloat16* dhi = (z == 0) ? g_qhi : (z == 1) ? g_khi : g_vhi;
    __nv_bfloat16* dlo = (z == 0) ? g_qlo : (z == 1) ? g_klo : g_vlo;

    if (z == 2) {
#pragma unroll
        for (int im = 0; im < 4; im++) {
            int r = r0 + im * 16;
            int b = r >> 11, s = r & 2047;     // SEQ = 2048; r,r+8 same batch
#pragma unroll
            for (int jn = 0; jn < 4; jn++) {
                int col = c0 + jn * 8;
                int h = col >> 6, d = col & 63;
                size_t off = ((size_t)(b * NUM_HEADS + h) * SEQ + s) * D_K + d;
                uint32_t hi, lo;
                split2(acc[im][jn][0], acc[im][jn][1], hi, lo);
                *(uint32_t*)(dhi + off) = hi;
                *(uint32_t*)(dlo + off) = lo;
                split2(acc[im][jn][2], acc[im][jn][3], hi, lo);
                *(uint32_t*)(dhi + off + (size_t)8 * D_K) = hi;
                *(uint32_t*)(dlo + off + (size_t)8 * D_K) = lo;
            }
        }
    } else {
        const float scale = (z == 0) ? 0.125f : 1.0f;
        float freqf[4];
#pragma unroll
        for (int jn = 0; jn < 4; jn++) {
            int j = ((c0 + jn * 8) & 63) >> 1;
            freqf[jn] = (float)exp((double)j * -0.28782313662425575);
        }
#pragma unroll
        for (int im = 0; im < 4; im++) {
            int r = r0 + im * 16;
            int b = r >> 11, s = r & 2047;
            float p0 = (float)pos[s];
            float p1 = (float)pos[s + 8];
#pragma unroll
            for (int jn = 0; jn < 4; jn++) {
                int col = c0 + jn * 8;
                int h = col >> 6, d = col & 63;
                size_t off = ((size_t)(b * NUM_HEADS + h) * SEQ + s) * D_K + d;
                float c, sn;
                sincosf(p0 * freqf[jn], &sn, &c);
                float x1 = acc[im][jn][0], x2 = acc[im][jn][1];
                uint32_t hi, lo;
                split2((x1 * c - x2 * sn) * scale, (x1 * sn + x2 * c) * scale, hi, lo);
                *(uint32_t*)(dhi + off) = hi;
                *(uint32_t*)(dlo + off) = lo;
                sincosf(p1 * freqf[jn], &sn, &c);
                x1 = acc[im][jn][2]; x2 = acc[im][jn][3];
                split2((x1 * c - x2 * sn) * scale, (x1 * sn + x2 * c) * scale, hi, lo);
                *(uint32_t*)(dhi + off + (size_t)8 * D_K) = hi;
                *(uint32_t*)(dlo + off + (size_t)8 * D_K) = lo;
            }
        }
    }
}

// Output projection: plain fp32 epilogue.
__global__ void __launch_bounds__(256) out_mma_kernel(float* __restrict__ out)
{
    extern __shared__ char smem[];
    const uint32_t sb = smem_u32(smem);
    const int bm = blockIdx.y * 128;
    const int bn = blockIdx.x * 128;
    const int tid  = threadIdx.x;
    const int wid  = tid >> 5;
    const int lane = tid & 31;
    const int wm = (wid >> 2) * 64;
    const int wn = (wid & 3) * 32;

    float acc[4][4][4];
    mma_mainloop(g_ahi, g_alo, &g_whi[3][0], &g_wlo[3][0], acc,
                 sb, bm, bn, tid, wm, wn, lane);

    const int r0 = bm + wm + (lane >> 2);
    const int c0 = bn + wn + (lane & 3) * 2;
#pragma unroll
    for (int im = 0; im < 4; im++)
#pragma unroll
        for (int jn = 0; jn < 4; jn++) {
            float* p0 = out + (size_t)(r0 + im * 16) * D_MODEL + c0 + jn * 8;
            float* p1 = out + (size_t)(r0 + im * 16 + 8) * D_MODEL + c0 + jn * 8;
            *(float2*)p0 = make_float2(acc[im][jn][0], acc[im][jn][1]);
            *(float2*)p1 = make_float2(acc[im][jn][2], acc[im][jn][3]);
        }
}

// ---------------- Flash attention (causal, HMMA bf16-split, 2-stage cp.async) --------
// Longest-first scheduling: qt = gridDim.x-1-blockIdx.x.
#define KH 0
#define KL 8192
#define VH 16384
#define VL 24576
#define FLASH_SMEM 65536

__global__ void __launch_bounds__(128) flash_kernel()
{
    extern __shared__ __align__(16) char fsm[];
    const uint32_t sb = smem_u32(fsm);

    const int qt = gridDim.x - 1 - blockIdx.x;   // longest-first
    const int h  = blockIdx.y;
    const int bb = blockIdx.z;
    const int tid  = threadIdx.x;
    const int wid  = tid >> 5;
    const int lane = tid & 31;

    const size_t hoff = (size_t)(bb * NUM_HEADS + h) * SEQ * D_K;
    const __nv_bfloat16* Qh = g_qhi + hoff;
    const __nv_bfloat16* Ql = g_qlo + hoff;
    const __nv_bfloat16* Kh = g_khi + hoff;
    const __nv_bfloat16* Kl = g_klo + hoff;
    const __nv_bfloat16* Vh = g_vhi + hoff;
    const __nv_bfloat16* Vl = g_vlo + hoff;
    const int q0 = qt * 64;

    const int rA = (lane & 7) + 8 * ((lane >> 3) & 1);
    const int pA = (lane >> 4) & 1;

    for (int i = tid; i < 512; i += 128) {
        int r = i >> 3, ch = i & 7;
        int sw = r * 128 + ((ch ^ (r & 7)) << 4);
        size_t gix = (size_t)(q0 + r) * D_K + ch * 8;
        cp_async16(sb + 32768 + KH + sw, Qh + gix);
        cp_async16(sb + 32768 + KL + sw, Ql + gix);
    }
    CP_COMMIT();
    for (int i = tid; i < 512; i += 128) {
        int r = i >> 3, ch = i & 7;
        int sw = r * 128 + ((ch ^ (r & 7)) << 4);
        size_t gix = (size_t)r * D_K + ch * 8;
        cp_async16(sb + KH + sw, Kh + gix);
        cp_async16(sb + KL + sw, Kl + gix);
        cp_async16(sb + VH + sw, Vh + gix);
        cp_async16(sb + VL + sw, Vl + gix);
    }
    CP_COMMIT();

    CP_WAIT(1);
    __syncthreads();

    uint32_t aq[4][4], aql[4][4];
#pragma unroll
    for (int ks = 0; ks < 4; ks++) {
        int slot = ks * 2 + pA;
        int row  = wid * 16 + rA;
        uint32_t ad = sb + 32768 + KH + row * 128 + ((slot ^ (row & 7)) << 4);
        ldmx4(aq[ks], ad);
        ldmx4(aql[ks], ad + (KL - KH));
    }

    float out[8][4];
#pragma unroll
    for (int g = 0; g < 8; g++)
#pragma unroll
        for (int e = 0; e < 4; e++) out[g][e] = 0.f;
    float m0 = -1e30f, m1 = -1e30f, l0 = 0.f, l1 = 0.f;

    for (int kt = 0; kt <= qt; kt++) {
        const uint32_t sbs = sb + (uint32_t)(kt & 1) * 32768;
        CP_WAIT(0);
        __syncthreads();

        if (kt < qt) {
            const uint32_t sbn = sb + (uint32_t)((kt + 1) & 1) * 32768;
            for (int i = tid; i < 512; i += 128) {
                int r = i >> 3, ch = i & 7;
                int sw = r * 128 + ((ch ^ (r & 7)) << 4);
                size_t gix = (size_t)((kt + 1) * 64 + r) * D_K + ch * 8;
                cp_async16(sbn + KH + sw, Kh + gix);
                cp_async16(sbn + KL + sw, Kl + gix);
                cp_async16(sbn + VH + sw, Vh + gix);
                cp_async16(sbn + VL + sw, Vl + gix);
            }
            CP_COMMIT();
        }

        float s[8][4];
#pragma unroll
        for (int g = 0; g < 8; g++)
#pragma unroll
            for (int e = 0; e < 4; e++) s[g][e] = 0.f;

#pragma unroll
        for (int ks = 0; ks < 4; ks++) {
            const int slot = ks * 2 + pA;
            uint32_t bh[8][2], bl[8][2];
#pragma unroll
            for (int g2 = 0; g2 < 4; g2++) {
                int row = g2 * 16 + rA;
                uint32_t bd = sbs + KH + row * 128 + ((slot ^ (row & 7)) << 4);
                uint32_t t0[4], t1[4];
                ldmx4(t0, bd);
                ldmx4(t1, bd + (KL - KH));
                bh[g2 * 2 + 0][0] = t0[0]; bh[g2 * 2 + 0][1] = t0[2];
                bh[g2 * 2 + 1][0] = t0[1]; bh[g2 * 2 + 1][1] = t0[3];
                bl[g2 * 2 + 0][0] = t1[0]; bl[g2 * 2 + 0][1] = t1[2];
                bl[g2 * 2 + 1][0] = t1[1]; bl[g2 * 2 + 1][1] = t1[3];
            }
#pragma unroll
            for (int g = 0; g < 8; g++) {
                mma_bf16(s[g], aq[ks], bh[g]);
                mma_bf16(s[g], aq[ks], bl[g]);
                mma_bf16(s[g], aql[ks], bh[g]);
            }
        }

        if (kt == qt) {
            int r0 = wid * 16 + (lane >> 2);
#pragma unroll
            for (int g = 0; g < 8; g++) {
                int cb = 8 * g + 2 * (lane & 3);
                if (cb     > r0)     s[g][0] = -1e30f;
                if (cb + 1 > r0)     s[g][1] = -1e30f;
                if (cb     > r0 + 8) s[g][2] = -1e30f;
                if (cb + 1 > r0 + 8) s[g][3] = -1e30f;
            }
        }

        float mx0 = -1e30f, mx1 = -1e30f;
#pragma unroll
        for (int g = 0; g < 8; g++) {
            mx0 = fmaxf(mx0, fmaxf(s[g][0], s[g][1]));
            mx1 = fmaxf(mx1, fmaxf(s[g][2], s[g][3]));
        }
        mx0 = fmaxf(mx0, __shfl_xor_sync(0xffffffffu, mx0, 1));
        mx0 = fmaxf(mx0, __shfl_xor_sync(0xffffffffu, mx0, 2));
        mx1 = fmaxf(mx1, __shfl_xor_sync(0xffffffffu, mx1, 1));
        mx1 = fmaxf(mx1, __shfl_xor_sync(0xffffffffu, mx1, 2));

        float mn0 = fmaxf(m0, mx0), mn1 = fmaxf(m1, mx1);
        float sf0 = __expf(m0 - mn0), sf1 = __expf(m1 - mn1);
        m0 = mn0; m1 = mn1;

        float rs0 = 0.f, rs1 = 0.f;
#pragma unroll
        for (int g = 0; g < 8; g++) {
            s[g][0] = __expf(s[g][0] - mn0);
            s[g][1] = __expf(s[g][1] - mn0);
            s[g][2] = __expf(s[g][2] - mn1);
            s[g][3] = __expf(s[g][3] - mn1);
            rs0 += s[g][0] + s[g][1];
            rs1 += s[g][2] + s[g][3];
        }
        rs0 += __shfl_xor_sync(0xffffffffu, rs0, 1);
        rs0 += __shfl_xor_sync(0xffffffffu, rs0, 2);
        rs1 += __shfl_xor_sync(0xffffffffu, rs1, 1);
        rs1 += __shfl_xor_sync(0xffffffffu, rs1, 2);
        l0 = l0 * sf0 + rs0;
        l1 = l1 * sf1 + rs1;
#pragma unroll
        for (int g = 0; g < 8; g++) {
            out[g][0] *= sf0; out[g][1] *= sf0;
            out[g][2] *= sf1; out[g][3] *= sf1;
        }

        uint32_t ap[4][4], apl[4][4];
#pragma unroll
        for (int j = 0; j < 4; j++) {
            split2(s[2*j][0],   s[2*j][1],   ap[j][0], apl[j][0]);
            split2(s[2*j][2],   s[2*j][3],   ap[j][1], apl[j][1]);
            split2(s[2*j+1][0], s[2*j+1][1], ap[j][2], apl[j][2]);
            split2(s[2*j+1][2], s[2*j+1][3], ap[j][3], apl[j][3]);
        }

#pragma unroll
        for (int j = 0; j < 4; j++) {
            uint32_t bv[8][2], bvl[8][2];
            int krow = j * 16 + (lane & 7) + 8 * ((lane >> 3) & 1);
            int colh = (lane >> 4) & 1;
#pragma unroll
            for (int dp = 0; dp < 4; dp++) {
                int slot = dp * 2 + colh;
                uint32_t ad = sbs + VH + krow * 128 + ((slot ^ (krow & 7)) << 4);
                uint32_t t0[4], t1[4];
                ldmx4t(t0, ad);
                ldmx4t(t1, ad + (VL - VH));
                bv[dp * 2 + 0][0] = t0[0]; bv[dp * 2 + 0][1] = t0[1];
                bv[dp * 2 + 1][0] = t0[2]; bv[dp * 2 + 1][1] = t0[3];
                bvl[dp * 2 + 0][0] = t1[0]; bvl[dp * 2 + 0][1] = t1[1];
                bvl[dp * 2 + 1][0] = t1[2]; bvl[dp * 2 + 1][1] = t1[3];
            }
#pragma unroll
            for (int g = 0; g < 8; g++) {
                mma_bf16(out[g], ap[j], bv[g]);
                mma_bf16(out[g], ap[j], bvl[g]);
                mma_bf16(out[g], apl[j], bv[g]);
            }
        }
    }

    float inv0 = 1.f / l0, inv1 = 1.f / l1;
    int srow = q0 + wid * 16 + (lane >> 2);
    size_t base0 = ((size_t)(bb * SEQ) + srow) * D_MODEL + h * 64;
    size_t base1 = base0 + (size_t)8 * D_MODEL;
#pragma unroll
    for (int g = 0; g < 8; g++) {
        int d = 8 * g + 2 * (lane & 3);
        uint32_t hi, lo;
        split2(out[g][0] * inv0, out[g][1] * inv0, hi, lo);
        *(uint32_t*)(g_ahi + base0 + d) = hi;
        *(uint32_t*)(g_alo + base0 + d) = lo;
        split2(out[g][2] * inv1, out[g][3] * inv1, hi, lo);
        *(uint32_t*)(g_ahi + base1 + d) = hi;
        *(uint32_t*)(g_alo + base1 + d) = lo;
    }
}

// ---------------- launch ----------------
extern "C" void kernel_launch(void* const* d_in, const int* in_sizes, int n_in,
                              void* d_out, int out_size)
{
    const float* x   = (const float*)d_in[0];
    const int*   pos = (const int*)  d_in[1];
    const float* wq  = (const float*)d_in[2];
    const float* wk  = (const float*)d_in[3];
    const float* wv  = (const float*)d_in[4];
    const float* wo  = (const float*)d_in[5];
    float* out = (float*)d_out;

    (void)in_sizes; (void)n_in; (void)out_size;

    static bool attr_done = false;
    if (!attr_done) {
        cudaFuncSetAttribute(qkv_mma_kernel, cudaFuncAttributeMaxDynamicSharedMemorySize,
                             GEMM_SMEM);
        cudaFuncSetAttribute(out_mma_kernel, cudaFuncAttributeMaxDynamicSharedMemorySize,
                             GEMM_SMEM);
        cudaFuncSetAttribute(flash_kernel, cudaFuncAttributeMaxDynamicSharedMemorySize,
                             FLASH_SMEM);
        attr_done = true;
    }

    __nv_bfloat16 *xhi, *xlo;
    cudaGetSymbolAddress((void**)&xhi, g_xhi);
    cudaGetSymbolAddress((void**)&xlo, g_xlo);

    const int n4x = M_TOK * D_MODEL / 4;
    const int n4w = D_MODEL * D_MODEL / 4;

    // 0) conversions: x (1 launch) + all 4 weights (1 launch)
    cvt_split_kernel<<<(n4x + 255) / 256, 256>>>((const float4*)x, xhi, xlo, n4x);
    cvt_w4_kernel<<<dim3((n4w + 255) / 256, 1, 4), 256>>>(
        (const float4*)wq, (const float4*)wk, (const float4*)wv, (const float4*)wo, n4w);

    // 1) QKV projections with fused RoPE + split epilogue
    qkv_mma_kernel<<<dim3(D_MODEL / 128, M_TOK / 128, 3), 256, GEMM_SMEM>>>(pos);

    // 2) flash attention (HMMA, 2-stage cp.async, longest-first)
    flash_kernel<<<dim3(SEQ / 64, NUM_HEADS, BATCH), 128, FLASH_SMEM>>>();

    // 3) output projection (HMMA)
    out_mma_kernel<<<dim3(D_MODEL / 128, M_TOK / 128, 1), 256, GEMM_SMEM>>>(out);
}